// round 14
// baseline (speedup 1.0000x reference)
#include <cuda_runtime.h>
#include <cuda_bf16.h>
#include <mma.h>
#include <math.h>
#include <stdint.h>

using namespace nvcuda;

// ===========================================================================
// DLRM forward. bf16 wmma GEMMs (CTA 128x128, BK=32, 4-stage, 4 warps x
// 64x64, 2 CTAs/SM) + cp.async-gathered tf32-gram interaction.
// ===========================================================================

#define BATCH      16384
#define EMB_DIM    128
#define TABLE_SIZE 100000
#define NUM_CAT    26
#define NUM_FEATS  27
#define TOP_IN     480
#define TOP_IN_P   512

// ------------------------- scratch (device globals) ------------------------
__device__ __nv_bfloat16 g_h1[BATCH * 512];
__device__ __nv_bfloat16 g_h2[BATCH * 256];
__device__ __nv_bfloat16 g_bot[BATCH * 128];
__device__ __nv_bfloat16 g_x [BATCH * TOP_IN_P];
__device__ __nv_bfloat16 g_t1[BATCH * 1024];
__device__ __nv_bfloat16 g_t2[BATCH * 1024];
__device__ __nv_bfloat16 g_t3[BATCH * 512];
__device__ __nv_bfloat16 g_t4[BATCH * 256];
__device__ __nv_bfloat16 g_bw2r[256 * 512];
__device__ __nv_bfloat16 g_bw3r[128 * 256];
__device__ __nv_bfloat16 g_tw1r[1024 * TOP_IN_P];
__device__ __nv_bfloat16 g_tw2r[1024 * 1024];
__device__ __nv_bfloat16 g_tw3r[512 * 1024];
__device__ __nv_bfloat16 g_tw4r[256 * 512];

// ------------------------------ helpers ------------------------------------
__device__ __forceinline__ uint32_t smem_u32(const void* p) {
    return (uint32_t)__cvta_generic_to_shared(p);
}
#define CP_ASYNC16(dst, src) \
    asm volatile("cp.async.cg.shared.global [%0], [%1], 16;" :: "r"(dst), "l"(src))
__device__ __forceinline__ void cp_commit() { asm volatile("cp.async.commit_group;"); }
__device__ __forceinline__ void cp_wait0_fn() { asm volatile("cp.async.wait_group 0;"); }
__device__ __forceinline__ void cp_wait_allow(int n) {
    if (n <= 0)      asm volatile("cp.async.wait_group 0;");
    else if (n == 1) asm volatile("cp.async.wait_group 1;");
    else             asm volatile("cp.async.wait_group 2;");
}

// ===========================================================================
// bf16 wmma GEMM (round-12 champion): CTA 128x128, BK=32, 4 stages,
// 4 warps x 64x64.
// ===========================================================================
#define LDM 40
#define STAGE_ELEMS (2 * 128 * LDM)
#define STAGE_BYTES (STAGE_ELEMS * 2)        // 20480
#define GEMM_SMEM   (4 * STAGE_BYTES)        // 81920

__global__ __launch_bounds__(128, 2)
void bf16_gemm(const __nv_bfloat16* __restrict__ A,
               const __nv_bfloat16* __restrict__ W,
               const float* __restrict__ bias,
               __nv_bfloat16* __restrict__ C,
               int N, int K) {
    extern __shared__ __nv_bfloat16 smem[];
    const int tid = threadIdx.x;
    const int warp = tid >> 5;
    const int bm = blockIdx.y * 128;
    const int bn = blockIdx.x * 128;
    const int wm = warp >> 1;
    const int wn = warp & 1;
    const uint32_t sb = smem_u32(smem);

    wmma::fragment<wmma::accumulator, 16, 16, 16, float> cf[4][4];
#pragma unroll
    for (int i = 0; i < 4; i++)
#pragma unroll
        for (int j = 0; j < 4; j++) wmma::fill_fragment(cf[i][j], 0.0f);

    const int T = K / 32;

    auto load_stage = [&](int t) {
        const int s = t & 3;
        const int k0 = t * 32;
        const uint32_t abase = sb + (uint32_t)s * STAGE_BYTES;
        const uint32_t bbase = abase + 128u * LDM * 2u;
#pragma unroll
        for (int i = 0; i < 4; i++) {
            int idx = tid + i * 128;
            int r = idx >> 2, c = idx & 3;
            CP_ASYNC16(abase + (uint32_t)(r * LDM + c * 8) * 2u,
                       A + (size_t)(bm + r) * K + k0 + c * 8);
        }
#pragma unroll
        for (int i = 0; i < 4; i++) {
            int idx = tid + i * 128;
            int r = idx >> 2, c = idx & 3;
            CP_ASYNC16(bbase + (uint32_t)(r * LDM + c * 8) * 2u,
                       W + (size_t)(bn + r) * K + k0 + c * 8);
        }
        cp_commit();
    };

    const int pre = T < 3 ? T : 3;
    for (int s = 0; s < pre; s++) load_stage(s);

    for (int t = 0; t < T; t++) {
        int allow = T - 1 - t; if (allow > 2) allow = 2;
        cp_wait_allow(allow);
        __syncthreads();
        if (t + 3 < T) load_stage(t + 3);

        const __nv_bfloat16* a = smem + (size_t)(t & 3) * STAGE_ELEMS;
        const __nv_bfloat16* b = a + 128 * LDM;
#pragma unroll
        for (int kk = 0; kk < 32; kk += 16) {
            wmma::fragment<wmma::matrix_a, 16, 16, 16, __nv_bfloat16, wmma::row_major> af[4];
            wmma::fragment<wmma::matrix_b, 16, 16, 16, __nv_bfloat16, wmma::col_major> bf[4];
#pragma unroll
            for (int i = 0; i < 4; i++)
                wmma::load_matrix_sync(af[i], a + (wm * 64 + i * 16) * LDM + kk, LDM);
#pragma unroll
            for (int j = 0; j < 4; j++)
                wmma::load_matrix_sync(bf[j], b + (wn * 64 + j * 16) * LDM + kk, LDM);
#pragma unroll
            for (int i = 0; i < 4; i++)
#pragma unroll
                for (int j = 0; j < 4; j++)
                    wmma::mma_sync(cf[i][j], af[i], bf[j], cf[i][j]);
        }
    }
    __syncthreads();

    // epilogue: fragments -> smem(fp32 128x132) -> bf16 gmem
    float* cs = (float*)smem;
#pragma unroll
    for (int i = 0; i < 4; i++)
#pragma unroll
        for (int j = 0; j < 4; j++)
            wmma::store_matrix_sync(cs + (size_t)(wm * 64 + i * 16) * 132 + wn * 64 + j * 16,
                                    cf[i][j], 132, wmma::mem_row_major);
    __syncthreads();

    {
        const int row = tid;
        const float* src = cs + (size_t)row * 132;
        __nv_bfloat16* dst = C + (size_t)(bm + row) * N + bn;
#pragma unroll
        for (int q = 0; q < 8; q++) {
            float4 v  = *(const float4*)(src + q * 16);
            float4 v1 = *(const float4*)(src + q * 16 + 4);
            float4 v2 = *(const float4*)(src + q * 16 + 8);
            float4 v3 = *(const float4*)(src + q * 16 + 12);
            float4 b0 = *(const float4*)(bias + bn + q * 16);
            float4 b1 = *(const float4*)(bias + bn + q * 16 + 4);
            float4 b2 = *(const float4*)(bias + bn + q * 16 + 8);
            float4 b3 = *(const float4*)(bias + bn + q * 16 + 12);
            v.x += b0.x;  v.y += b0.y;  v.z += b0.z;  v.w += b0.w;
            v1.x += b1.x; v1.y += b1.y; v1.z += b1.z; v1.w += b1.w;
            v2.x += b2.x; v2.y += b2.y; v2.z += b2.z; v2.w += b2.w;
            v3.x += b3.x; v3.y += b3.y; v3.z += b3.z; v3.w += b3.w;
            v.x = v.x > 0.f ? v.x : 0.f;   v.y = v.y > 0.f ? v.y : 0.f;
            v.z = v.z > 0.f ? v.z : 0.f;   v.w = v.w > 0.f ? v.w : 0.f;
            v1.x = v1.x > 0.f ? v1.x : 0.f; v1.y = v1.y > 0.f ? v1.y : 0.f;
            v1.z = v1.z > 0.f ? v1.z : 0.f; v1.w = v1.w > 0.f ? v1.w : 0.f;
            v2.x = v2.x > 0.f ? v2.x : 0.f; v2.y = v2.y > 0.f ? v2.y : 0.f;
            v2.z = v2.z > 0.f ? v2.z : 0.f; v2.w = v2.w > 0.f ? v2.w : 0.f;
            v3.x = v3.x > 0.f ? v3.x : 0.f; v3.y = v3.y > 0.f ? v3.y : 0.f;
            v3.z = v3.z > 0.f ? v3.z : 0.f; v3.w = v3.w > 0.f ? v3.w : 0.f;
            __nv_bfloat162 p0 = __floats2bfloat162_rn(v.x, v.y);
            __nv_bfloat162 p1 = __floats2bfloat162_rn(v.z, v.w);
            __nv_bfloat162 p2 = __floats2bfloat162_rn(v1.x, v1.y);
            __nv_bfloat162 p3 = __floats2bfloat162_rn(v1.z, v1.w);
            __nv_bfloat162 p4 = __floats2bfloat162_rn(v2.x, v2.y);
            __nv_bfloat162 p5 = __floats2bfloat162_rn(v2.z, v2.w);
            __nv_bfloat162 p6 = __floats2bfloat162_rn(v3.x, v3.y);
            __nv_bfloat162 p7 = __floats2bfloat162_rn(v3.z, v3.w);
            uint4 pk0, pk1;
            pk0.x = *(uint32_t*)&p0; pk0.y = *(uint32_t*)&p1;
            pk0.z = *(uint32_t*)&p2; pk0.w = *(uint32_t*)&p3;
            pk1.x = *(uint32_t*)&p4; pk1.y = *(uint32_t*)&p5;
            pk1.z = *(uint32_t*)&p6; pk1.w = *(uint32_t*)&p7;
            *(uint4*)(dst + q * 16)     = pk0;
            *(uint4*)(dst + q * 16 + 8) = pk1;
        }
    }
}

// ===========================================================================
// Fused L1 SGEMM (K=13) + weight rounding (blockIdx.y >= 128).
// ===========================================================================
#define RW_N0 131072
#define RW_N1 32768
#define RW_N2 (1024 * TOP_IN_P)
#define RW_N3 1048576
#define RW_N4 524288
#define RW_N5 131072
#define RW_TOTAL (RW_N0 + RW_N1 + RW_N2 + RW_N3 + RW_N4 + RW_N5)
#define RB_Y 128

__global__ __launch_bounds__(256, 2)
void l1_and_round(const float* __restrict__ A, const float* __restrict__ W,
                  const float* __restrict__ bias, __nv_bfloat16* __restrict__ C,
                  const float* __restrict__ bw2, const float* __restrict__ bw3,
                  const float* __restrict__ tw1, const float* __restrict__ tw2,
                  const float* __restrict__ tw3, const float* __restrict__ tw4,
                  __nv_bfloat16* __restrict__ d0, __nv_bfloat16* __restrict__ d1,
                  __nv_bfloat16* __restrict__ d2, __nv_bfloat16* __restrict__ d3,
                  __nv_bfloat16* __restrict__ d4, __nv_bfloat16* __restrict__ d5) {
    const int tid = threadIdx.x;

    if (blockIdx.y >= BATCH / 128) {
        const int nrb = 4 * RB_Y;
        const int rb = (blockIdx.y - BATCH / 128) * 4 + blockIdx.x;
        const int stride = nrb * 256;
        for (int i = rb * 256 + tid; i < RW_TOTAL; i += stride) {
            int j = i;
            if (j < RW_N0) { d0[j] = __float2bfloat16(bw2[j]); continue; }
            j -= RW_N0;
            if (j < RW_N1) { d1[j] = __float2bfloat16(bw3[j]); continue; }
            j -= RW_N1;
            if (j < RW_N2) {
                int n = j / TOP_IN_P, k = j % TOP_IN_P;
                d2[j] = (k < TOP_IN) ? __float2bfloat16(tw1[n * TOP_IN + k])
                                     : __float2bfloat16(0.f);
                continue;
            }
            j -= RW_N2;
            if (j < RW_N3) { d3[j] = __float2bfloat16(tw2[j]); continue; }
            j -= RW_N3;
            if (j < RW_N4) { d4[j] = __float2bfloat16(tw3[j]); continue; }
            j -= RW_N4;
            d5[j] = __float2bfloat16(tw4[j]);
        }
        return;
    }

    const int N = 512, K = 13;
    __shared__ float As[8][132];
    __shared__ float Bs[8][132];
    const int bm = blockIdx.y * 128, bn = blockIdx.x * 128;
    const int tx = tid & 15, ty = tid >> 4;
    const int lk = tid & 7, lr = tid >> 3;

    float acc[8][8];
#pragma unroll
    for (int i = 0; i < 8; i++)
#pragma unroll
        for (int j = 0; j < 8; j++) acc[i][j] = 0.f;

    for (int k0 = 0; k0 < K; k0 += 8) {
        const int kk = k0 + lk;
        const bool kv = (kk < K);
#pragma unroll
        for (int p = 0; p < 4; p++) {
            const int row = lr + p * 32;
            As[lk][row] = kv ? A[(size_t)(bm + row) * K + kk] : 0.f;
            Bs[lk][row] = kv ? W[(size_t)(bn + row) * K + kk] : 0.f;
        }
        __syncthreads();
#pragma unroll
        for (int k = 0; k < 8; k++) {
            float4 a0 = *(const float4*)&As[k][ty * 4];
            float4 a1 = *(const float4*)&As[k][64 + ty * 4];
            float4 b0 = *(const float4*)&Bs[k][tx * 4];
            float4 b1 = *(const float4*)&Bs[k][64 + tx * 4];
            float a[8] = {a0.x, a0.y, a0.z, a0.w, a1.x, a1.y, a1.z, a1.w};
            float b[8] = {b0.x, b0.y, b0.z, b0.w, b1.x, b1.y, b1.z, b1.w};
#pragma unroll
            for (int i = 0; i < 8; i++)
#pragma unroll
                for (int j = 0; j < 8; j++)
                    acc[i][j] += a[i] * b[j];
        }
        __syncthreads();
    }
    const int rbase[2] = {bm + ty * 4, bm + 64 + ty * 4};
    const int cbase[2] = {bn + tx * 4, bn + 64 + tx * 4};
#pragma unroll
    for (int jh = 0; jh < 2; jh++) {
        const int col = cbase[jh];
        float4 bv = *(const float4*)&bias[col];
#pragma unroll
        for (int ih = 0; ih < 2; ih++) {
#pragma unroll
            for (int i = 0; i < 4; i++) {
                const int row = rbase[ih] + i;
                float4 v;
                v.x = acc[ih * 4 + i][jh * 4 + 0] + bv.x;
                v.y = acc[ih * 4 + i][jh * 4 + 1] + bv.y;
                v.z = acc[ih * 4 + i][jh * 4 + 2] + bv.z;
                v.w = acc[ih * 4 + i][jh * 4 + 3] + bv.w;
                v.x = v.x > 0.f ? v.x : 0.f;
                v.y = v.y > 0.f ? v.y : 0.f;
                v.z = v.z > 0.f ? v.z : 0.f;
                v.w = v.w > 0.f ? v.w : 0.f;
                __nv_bfloat162 p0 = __floats2bfloat162_rn(v.x, v.y);
                __nv_bfloat162 p1 = __floats2bfloat162_rn(v.z, v.w);
                uint2 pk; pk.x = *(uint32_t*)&p0; pk.y = *(uint32_t*)&p1;
                *(uint2*)&C[(size_t)row * N + col] = pk;
            }
        }
    }
}

// ===========================================================================
// interact6: cp.async gather into fp32 smem, tf32 wmma gram (RNA-rounded
// fragments). 128 thr = 4 warps = 4 samples/CTA; 3 CTAs/SM. No CTA barriers.
// ===========================================================================
#define IF32 132                               // fp32 row stride (528 B)
#define INTERACT_SMEM (4 * 32 * IF32 * 4)      // 67584

__global__ __launch_bounds__(128, 3)
void interact6(const __nv_bfloat16* __restrict__ bottom,
               const int* __restrict__ cat,
               const float* __restrict__ emb,
               __nv_bfloat16* __restrict__ x) {
    extern __shared__ float fsm[];
    const int warp = threadIdx.x >> 5, lane = threadIdx.x & 31;
    const int b = blockIdx.x * 4 + warp;
    float* fs = fsm + (size_t)warp * 32 * IF32;
    const uint32_t fsb = smem_u32(fs);

    int ci = 0;
    if (lane < NUM_CAT) ci = cat[(size_t)lane * BATCH + b];

    // rows 1..26 via cp.async: 26 x 512 B per warp, all in flight at once
#pragma unroll
    for (int r = 1; r <= 26; r++) {
        const int idx = __shfl_sync(0xffffffffu, ci, r - 1);
        CP_ASYNC16(fsb + (uint32_t)(r * IF32 + lane * 4) * 4u,
                   emb + ((size_t)(r - 1) * TABLE_SIZE + idx) * 128 + lane * 4);
    }
    cp_commit();

    // row 0: bottom bf16 -> fp32 (while gathers are in flight)
    {
        uint2 raw = *(const uint2*)(bottom + (size_t)b * 128 + lane * 4);
        __nv_bfloat162 p0 = *(__nv_bfloat162*)&raw.x;
        __nv_bfloat162 p1 = *(__nv_bfloat162*)&raw.y;
        float4 v;
        v.x = __bfloat162float(p0.x); v.y = __bfloat162float(p0.y);
        v.z = __bfloat162float(p1.x); v.w = __bfloat162float(p1.y);
        *(float4*)(fs + lane * 4) = v;
    }
    // zero rows 27..31 (5 * 132 = 660 floats = 165 float4)
    {
        float4 z; z.x = z.y = z.z = z.w = 0.f;
        for (int i = lane; i < 5 * IF32 / 4; i += 32)
            *(float4*)(fs + 27 * IF32 + i * 4) = z;
    }
    cp_wait0_fn();
    __syncwarp();

    // gram: G = F F^T in tf32 (m16n16k8), fragments RNA-rounded
    wmma::fragment<wmma::accumulator, 16, 16, 8, float> g00, g10, g11;
    wmma::fill_fragment(g00, 0.0f);
    wmma::fill_fragment(g10, 0.0f);
    wmma::fill_fragment(g11, 0.0f);
#pragma unroll
    for (int kk = 0; kk < 128; kk += 8) {
        wmma::fragment<wmma::matrix_a, 16, 16, 8, wmma::precision::tf32, wmma::row_major> a0, a1;
        wmma::fragment<wmma::matrix_b, 16, 16, 8, wmma::precision::tf32, wmma::col_major> b0, b1;
        wmma::load_matrix_sync(a0, fs + kk, IF32);
        wmma::load_matrix_sync(a1, fs + 16 * IF32 + kk, IF32);
        wmma::load_matrix_sync(b0, fs + kk, IF32);
        wmma::load_matrix_sync(b1, fs + 16 * IF32 + kk, IF32);
#pragma unroll
        for (int t = 0; t < a0.num_elements; t++) {
            a0.x[t] = wmma::__float_to_tf32(a0.x[t]);
            a1.x[t] = wmma::__float_to_tf32(a1.x[t]);
        }
#pragma unroll
        for (int t = 0; t < b0.num_elements; t++) {
            b0.x[t] = wmma::__float_to_tf32(b0.x[t]);
            b1.x[t] = wmma::__float_to_tf32(b1.x[t]);
        }
        wmma::mma_sync(g00, a0, b0, g00);
        wmma::mma_sync(g10, a1, b0, g10);
        wmma::mma_sync(g11, a1, b1, g11);
    }

    // stage G into this warp's smem patch (32*34*4 = 4352 B)
    float* gs = fs;
    wmma::store_matrix_sync(gs, g00, 34, wmma::mem_row_major);
    wmma::store_matrix_sync(gs + 16 * 34, g10, 34, wmma::mem_row_major);
    wmma::store_matrix_sync(gs + 16 * 34 + 16, g11, 34, wmma::mem_row_major);
    __syncwarp();

    // outputs
    __nv_bfloat16* xb = x + (size_t)b * TOP_IN_P;
    *(uint2*)(xb + lane * 4) = *(const uint2*)(bottom + (size_t)b * 128 + lane * 4);
    if (lane < 8) {
        uint2 z; z.x = 0u; z.y = 0u;
        *(uint2*)(xb + 480 + lane * 4) = z;
    } else if (lane == 8) {
        xb[TOP_IN - 1] = __float2bfloat16(0.f);
    }
    for (int p = lane; p < 351; p += 32) {
        int r = (int)((1.0f + sqrtf(8.0f * (float)p + 1.0f)) * 0.5f);
        if (r * (r - 1) / 2 > p) r--;
        if ((r + 1) * r / 2 <= p) r++;
        const int c = p - r * (r - 1) / 2;
        xb[128 + p] = __float2bfloat16(gs[r * 34 + c]);
    }
}

// ===========================================================================
// Final layer: sigmoid(dot(t4_bf16, w5) + b5). Warp per sample.
// ===========================================================================
__global__ __launch_bounds__(256)
void final_layer(const __nv_bfloat16* __restrict__ A,
                 const float* __restrict__ w5,
                 const float* __restrict__ b5, float* __restrict__ out) {
    const int gwarp = (blockIdx.x * blockDim.x + threadIdx.x) >> 5;
    const int lane = threadIdx.x & 31;
    if (gwarp >= BATCH) return;
    uint4 raw = *(const uint4*)(A + (size_t)gwarp * 256 + lane * 8);
    const float4* w4 = (const float4*)(w5 + lane * 8);
    float4 w0 = w4[0], w1 = w4[1];
    __nv_bfloat162 p0 = *(__nv_bfloat162*)&raw.x;
    __nv_bfloat162 p1 = *(__nv_bfloat162*)&raw.y;
    __nv_bfloat162 p2 = *(__nv_bfloat162*)&raw.z;
    __nv_bfloat162 p3 = *(__nv_bfloat162*)&raw.w;
    float s = __bfloat162float(p0.x) * w0.x + __bfloat162float(p0.y) * w0.y +
              __bfloat162float(p1.x) * w0.z + __bfloat162float(p1.y) * w0.w +
              __bfloat162float(p2.x) * w1.x + __bfloat162float(p2.y) * w1.y +
              __bfloat162float(p3.x) * w1.z + __bfloat162float(p3.y) * w1.w;
#pragma unroll
    for (int o = 16; o; o >>= 1) s += __shfl_xor_sync(0xffffffffu, s, o);
    if (lane == 0) out[gwarp] = 1.f / (1.f + expf(-(s + b5[0])));
}

// ===========================================================================
extern "C" void kernel_launch(void* const* d_in, const int* in_sizes, int n_in,
                              void* d_out, int out_size) {
    const float* num = (const float*)d_in[0];
    const int*   cat = (const int*)  d_in[1];
    const float* emb = (const float*)d_in[2];
    const float* bw1 = (const float*)d_in[3];
    const float* bb1 = (const float*)d_in[4];
    const float* bw2 = (const float*)d_in[5];
    const float* bb2 = (const float*)d_in[6];
    const float* bw3 = (const float*)d_in[7];
    const float* bb3 = (const float*)d_in[8];
    const float* tw1 = (const float*)d_in[9];
    const float* tb1 = (const float*)d_in[10];
    const float* tw2 = (const float*)d_in[11];
    const float* tb2 = (const float*)d_in[12];
    const float* tw3 = (const float*)d_in[13];
    const float* tb3 = (const float*)d_in[14];
    const float* tw4 = (const float*)d_in[15];
    const float* tb4 = (const float*)d_in[16];
    const float* tw5 = (const float*)d_in[17];
    const float* tb5 = (const float*)d_in[18];
    float* out = (float*)d_out;

    __nv_bfloat16 *h1, *h2, *bot, *x, *t1, *t2, *t3, *t4;
    __nv_bfloat16 *bw2r, *bw3r, *tw1r, *tw2r, *tw3r, *tw4r;
    cudaGetSymbolAddress((void**)&h1,  g_h1);
    cudaGetSymbolAddress((void**)&h2,  g_h2);
    cudaGetSymbolAddress((void**)&bot, g_bot);
    cudaGetSymbolAddress((void**)&x,   g_x);
    cudaGetSymbolAddress((void**)&t1,  g_t1);
    cudaGetSymbolAddress((void**)&t2,  g_t2);
    cudaGetSymbolAddress((void**)&t3,  g_t3);
    cudaGetSymbolAddress((void**)&t4,  g_t4);
    cudaGetSymbolAddress((void**)&bw2r, g_bw2r);
    cudaGetSymbolAddress((void**)&bw3r, g_bw3r);
    cudaGetSymbolAddress((void**)&tw1r, g_tw1r);
    cudaGetSymbolAddress((void**)&tw2r, g_tw2r);
    cudaGetSymbolAddress((void**)&tw3r, g_tw3r);
    cudaGetSymbolAddress((void**)&tw4r, g_tw4r);

    cudaFuncSetAttribute(bf16_gemm, cudaFuncAttributeMaxDynamicSharedMemorySize, GEMM_SMEM);
    cudaFuncSetAttribute(interact6, cudaFuncAttributeMaxDynamicSharedMemorySize, INTERACT_SMEM);

    const int MB = BATCH / 128;  // 128

    // launch 1: L1 SGEMM + weight rounding (fused)
    l1_and_round<<<dim3(4, MB + RB_Y), 256>>>(num, bw1, bb1, h1,
                                              bw2, bw3, tw1, tw2, tw3, tw4,
                                              bw2r, bw3r, tw1r, tw2r, tw3r, tw4r);

    // launches 2-3: bottom MLP
    bf16_gemm<<<dim3(2, MB), 128, GEMM_SMEM>>>(h1, bw2r, bb2, h2, 256, 512);
    bf16_gemm<<<dim3(1, MB), 128, GEMM_SMEM>>>(h2, bw3r, bb3, bot, 128, 256);

    // launch 4 (profiled): interaction
    interact6<<<BATCH / 4, 128, INTERACT_SMEM>>>(bot, cat, emb, x);

    // top MLP
    bf16_gemm<<<dim3(8, MB), 128, GEMM_SMEM>>>(x,  tw1r, tb1, t1, 1024, TOP_IN_P);
    bf16_gemm<<<dim3(8, MB), 128, GEMM_SMEM>>>(t1, tw2r, tb2, t2, 1024, 1024);
    bf16_gemm<<<dim3(4, MB), 128, GEMM_SMEM>>>(t2, tw3r, tb3, t3, 512, 1024);
    bf16_gemm<<<dim3(2, MB), 128, GEMM_SMEM>>>(t3, tw4r, tb4, t4, 256, 512);

    // final dot + sigmoid
    final_layer<<<(BATCH * 32 + 255) / 256, 256>>>(t4, tw5, tb5, out);
}

// round 15
// speedup vs baseline: 1.0237x; 1.0237x over previous
#include <cuda_runtime.h>
#include <cuda_bf16.h>
#include <mma.h>
#include <math.h>
#include <stdint.h>

using namespace nvcuda;

// ===========================================================================
// DLRM forward. bf16 wmma GEMMs: CTA 128x128, BK=64, 3-stage cp.async,
// 4 warps x 64x64 warp-tiles, 2 CTAs/SM. interact5 (register-batched gather).
// ===========================================================================

#define BATCH      16384
#define EMB_DIM    128
#define TABLE_SIZE 100000
#define NUM_CAT    26
#define NUM_FEATS  27
#define TOP_IN     480
#define TOP_IN_P   512

// ------------------------- scratch (device globals) ------------------------
__device__ __nv_bfloat16 g_h1[BATCH * 512];
__device__ __nv_bfloat16 g_h2[BATCH * 256];
__device__ __nv_bfloat16 g_bot[BATCH * 128];
__device__ __nv_bfloat16 g_x [BATCH * TOP_IN_P];
__device__ __nv_bfloat16 g_t1[BATCH * 1024];
__device__ __nv_bfloat16 g_t2[BATCH * 1024];
__device__ __nv_bfloat16 g_t3[BATCH * 512];
__device__ __nv_bfloat16 g_t4[BATCH * 256];
__device__ __nv_bfloat16 g_bw2r[256 * 512];
__device__ __nv_bfloat16 g_bw3r[128 * 256];
__device__ __nv_bfloat16 g_tw1r[1024 * TOP_IN_P];
__device__ __nv_bfloat16 g_tw2r[1024 * 1024];
__device__ __nv_bfloat16 g_tw3r[512 * 1024];
__device__ __nv_bfloat16 g_tw4r[256 * 512];

// ------------------------------ helpers ------------------------------------
__device__ __forceinline__ uint32_t smem_u32(const void* p) {
    return (uint32_t)__cvta_generic_to_shared(p);
}
#define CP_ASYNC16(dst, src) \
    asm volatile("cp.async.cg.shared.global [%0], [%1], 16;" :: "r"(dst), "l"(src))
__device__ __forceinline__ void cp_commit() { asm volatile("cp.async.commit_group;"); }
__device__ __forceinline__ void cp_wait_allow(int n) {
    if (n <= 0)      asm volatile("cp.async.wait_group 0;");
    else             asm volatile("cp.async.wait_group 1;");
}

// ===========================================================================
// bf16 wmma GEMM: CTA 128x128, BK=64, 3-stage cp.async, 4 warps x 64x64.
// LDM=72 (144B rows, ldmatrix conflict-free). Stage 36864 B, 3 stages.
// Requires M%128==0, N%128==0, K%64==0.
// ===========================================================================
#define LDM 72
#define STAGE_ELEMS (2 * 128 * LDM)          // 18432 bf16
#define STAGE_BYTES (STAGE_ELEMS * 2)        // 36864
#define GEMM_SMEM   (3 * STAGE_BYTES)        // 110592

__global__ __launch_bounds__(128, 2)
void bf16_gemm(const __nv_bfloat16* __restrict__ A,
               const __nv_bfloat16* __restrict__ W,
               const float* __restrict__ bias,
               __nv_bfloat16* __restrict__ C,
               int N, int K) {
    extern __shared__ __nv_bfloat16 smem[];
    const int tid = threadIdx.x;
    const int warp = tid >> 5;
    const int bm = blockIdx.y * 128;
    const int bn = blockIdx.x * 128;
    const int wm = warp >> 1;
    const int wn = warp & 1;
    const uint32_t sb = smem_u32(smem);

    wmma::fragment<wmma::accumulator, 16, 16, 16, float> cf[4][4];
#pragma unroll
    for (int i = 0; i < 4; i++)
#pragma unroll
        for (int j = 0; j < 4; j++) wmma::fill_fragment(cf[i][j], 0.0f);

    const int T = K / 64;

    // per stage: A 128 rows x 8 chunks(16B) + B same = 2048 cp; 128 thr x 16
    auto load_stage = [&](int t) {
        const int s = t % 3;
        const int k0 = t * 64;
        const uint32_t abase = sb + (uint32_t)s * STAGE_BYTES;
        const uint32_t bbase = abase + 128u * LDM * 2u;
#pragma unroll
        for (int i = 0; i < 8; i++) {
            int idx = tid + i * 128;
            int r = idx >> 3, c = idx & 7;
            CP_ASYNC16(abase + (uint32_t)(r * LDM + c * 8) * 2u,
                       A + (size_t)(bm + r) * K + k0 + c * 8);
        }
#pragma unroll
        for (int i = 0; i < 8; i++) {
            int idx = tid + i * 128;
            int r = idx >> 3, c = idx & 7;
            CP_ASYNC16(bbase + (uint32_t)(r * LDM + c * 8) * 2u,
                       W + (size_t)(bn + r) * K + k0 + c * 8);
        }
        cp_commit();
    };

    const int pre = T < 2 ? T : 2;
    for (int s = 0; s < pre; s++) load_stage(s);

    for (int t = 0; t < T; t++) {
        int allow = T - 1 - t; if (allow > 1) allow = 1;
        cp_wait_allow(allow);        // stage t arrived
        __syncthreads();             // all warps done with stage t-1
        if (t + 2 < T) load_stage(t + 2);   // buf (t+2)%3 == (t-1)%3: safe

        const __nv_bfloat16* a = smem + (size_t)(t % 3) * STAGE_ELEMS;
        const __nv_bfloat16* b = a + 128 * LDM;
#pragma unroll
        for (int kk = 0; kk < 64; kk += 16) {
            wmma::fragment<wmma::matrix_a, 16, 16, 16, __nv_bfloat16, wmma::row_major> af[4];
            wmma::fragment<wmma::matrix_b, 16, 16, 16, __nv_bfloat16, wmma::col_major> bf[4];
#pragma unroll
            for (int i = 0; i < 4; i++)
                wmma::load_matrix_sync(af[i], a + (wm * 64 + i * 16) * LDM + kk, LDM);
#pragma unroll
            for (int j = 0; j < 4; j++)
                wmma::load_matrix_sync(bf[j], b + (wn * 64 + j * 16) * LDM + kk, LDM);
#pragma unroll
            for (int i = 0; i < 4; i++)
#pragma unroll
                for (int j = 0; j < 4; j++)
                    wmma::mma_sync(cf[i][j], af[i], bf[j], cf[i][j]);
        }
    }
    __syncthreads();

    // epilogue: fragments -> smem(fp32 128x132 = 67584 B) -> bf16 gmem
    float* cs = (float*)smem;
#pragma unroll
    for (int i = 0; i < 4; i++)
#pragma unroll
        for (int j = 0; j < 4; j++)
            wmma::store_matrix_sync(cs + (size_t)(wm * 64 + i * 16) * 132 + wn * 64 + j * 16,
                                    cf[i][j], 132, wmma::mem_row_major);
    __syncthreads();

    {
        const int row = tid;
        const float* src = cs + (size_t)row * 132;
        __nv_bfloat16* dst = C + (size_t)(bm + row) * N + bn;
#pragma unroll
        for (int q = 0; q < 8; q++) {
            float4 v  = *(const float4*)(src + q * 16);
            float4 v1 = *(const float4*)(src + q * 16 + 4);
            float4 v2 = *(const float4*)(src + q * 16 + 8);
            float4 v3 = *(const float4*)(src + q * 16 + 12);
            float4 b0 = *(const float4*)(bias + bn + q * 16);
            float4 b1 = *(const float4*)(bias + bn + q * 16 + 4);
            float4 b2 = *(const float4*)(bias + bn + q * 16 + 8);
            float4 b3 = *(const float4*)(bias + bn + q * 16 + 12);
            v.x += b0.x;  v.y += b0.y;  v.z += b0.z;  v.w += b0.w;
            v1.x += b1.x; v1.y += b1.y; v1.z += b1.z; v1.w += b1.w;
            v2.x += b2.x; v2.y += b2.y; v2.z += b2.z; v2.w += b2.w;
            v3.x += b3.x; v3.y += b3.y; v3.z += b3.z; v3.w += b3.w;
            v.x = v.x > 0.f ? v.x : 0.f;   v.y = v.y > 0.f ? v.y : 0.f;
            v.z = v.z > 0.f ? v.z : 0.f;   v.w = v.w > 0.f ? v.w : 0.f;
            v1.x = v1.x > 0.f ? v1.x : 0.f; v1.y = v1.y > 0.f ? v1.y : 0.f;
            v1.z = v1.z > 0.f ? v1.z : 0.f; v1.w = v1.w > 0.f ? v1.w : 0.f;
            v2.x = v2.x > 0.f ? v2.x : 0.f; v2.y = v2.y > 0.f ? v2.y : 0.f;
            v2.z = v2.z > 0.f ? v2.z : 0.f; v2.w = v2.w > 0.f ? v2.w : 0.f;
            v3.x = v3.x > 0.f ? v3.x : 0.f; v3.y = v3.y > 0.f ? v3.y : 0.f;
            v3.z = v3.z > 0.f ? v3.z : 0.f; v3.w = v3.w > 0.f ? v3.w : 0.f;
            __nv_bfloat162 p0 = __floats2bfloat162_rn(v.x, v.y);
            __nv_bfloat162 p1 = __floats2bfloat162_rn(v.z, v.w);
            __nv_bfloat162 p2 = __floats2bfloat162_rn(v1.x, v1.y);
            __nv_bfloat162 p3 = __floats2bfloat162_rn(v1.z, v1.w);
            __nv_bfloat162 p4 = __floats2bfloat162_rn(v2.x, v2.y);
            __nv_bfloat162 p5 = __floats2bfloat162_rn(v2.z, v2.w);
            __nv_bfloat162 p6 = __floats2bfloat162_rn(v3.x, v3.y);
            __nv_bfloat162 p7 = __floats2bfloat162_rn(v3.z, v3.w);
            uint4 pk0, pk1;
            pk0.x = *(uint32_t*)&p0; pk0.y = *(uint32_t*)&p1;
            pk0.z = *(uint32_t*)&p2; pk0.w = *(uint32_t*)&p3;
            pk1.x = *(uint32_t*)&p4; pk1.y = *(uint32_t*)&p5;
            pk1.z = *(uint32_t*)&p6; pk1.w = *(uint32_t*)&p7;
            *(uint4*)(dst + q * 16)     = pk0;
            *(uint4*)(dst + q * 16 + 8) = pk1;
        }
    }
}

// ===========================================================================
// Fused L1 SGEMM (K=13) + weight rounding (blockIdx.y >= 128).
// ===========================================================================
#define RW_N0 131072
#define RW_N1 32768
#define RW_N2 (1024 * TOP_IN_P)
#define RW_N3 1048576
#define RW_N4 524288
#define RW_N5 131072
#define RW_TOTAL (RW_N0 + RW_N1 + RW_N2 + RW_N3 + RW_N4 + RW_N5)
#define RB_Y 128

__global__ __launch_bounds__(256, 2)
void l1_and_round(const float* __restrict__ A, const float* __restrict__ W,
                  const float* __restrict__ bias, __nv_bfloat16* __restrict__ C,
                  const float* __restrict__ bw2, const float* __restrict__ bw3,
                  const float* __restrict__ tw1, const float* __restrict__ tw2,
                  const float* __restrict__ tw3, const float* __restrict__ tw4,
                  __nv_bfloat16* __restrict__ d0, __nv_bfloat16* __restrict__ d1,
                  __nv_bfloat16* __restrict__ d2, __nv_bfloat16* __restrict__ d3,
                  __nv_bfloat16* __restrict__ d4, __nv_bfloat16* __restrict__ d5) {
    const int tid = threadIdx.x;

    if (blockIdx.y >= BATCH / 128) {
        const int nrb = 4 * RB_Y;
        const int rb = (blockIdx.y - BATCH / 128) * 4 + blockIdx.x;
        const int stride = nrb * 256;
        for (int i = rb * 256 + tid; i < RW_TOTAL; i += stride) {
            int j = i;
            if (j < RW_N0) { d0[j] = __float2bfloat16(bw2[j]); continue; }
            j -= RW_N0;
            if (j < RW_N1) { d1[j] = __float2bfloat16(bw3[j]); continue; }
            j -= RW_N1;
            if (j < RW_N2) {
                int n = j / TOP_IN_P, k = j % TOP_IN_P;
                d2[j] = (k < TOP_IN) ? __float2bfloat16(tw1[n * TOP_IN + k])
                                     : __float2bfloat16(0.f);
                continue;
            }
            j -= RW_N2;
            if (j < RW_N3) { d3[j] = __float2bfloat16(tw2[j]); continue; }
            j -= RW_N3;
            if (j < RW_N4) { d4[j] = __float2bfloat16(tw3[j]); continue; }
            j -= RW_N4;
            d5[j] = __float2bfloat16(tw4[j]);
        }
        return;
    }

    const int N = 512, K = 13;
    __shared__ float As[8][132];
    __shared__ float Bs[8][132];
    const int bm = blockIdx.y * 128, bn = blockIdx.x * 128;
    const int tx = tid & 15, ty = tid >> 4;
    const int lk = tid & 7, lr = tid >> 3;

    float acc[8][8];
#pragma unroll
    for (int i = 0; i < 8; i++)
#pragma unroll
        for (int j = 0; j < 8; j++) acc[i][j] = 0.f;

    for (int k0 = 0; k0 < K; k0 += 8) {
        const int kk = k0 + lk;
        const bool kv = (kk < K);
#pragma unroll
        for (int p = 0; p < 4; p++) {
            const int row = lr + p * 32;
            As[lk][row] = kv ? A[(size_t)(bm + row) * K + kk] : 0.f;
            Bs[lk][row] = kv ? W[(size_t)(bn + row) * K + kk] : 0.f;
        }
        __syncthreads();
#pragma unroll
        for (int k = 0; k < 8; k++) {
            float4 a0 = *(const float4*)&As[k][ty * 4];
            float4 a1 = *(const float4*)&As[k][64 + ty * 4];
            float4 b0 = *(const float4*)&Bs[k][tx * 4];
            float4 b1 = *(const float4*)&Bs[k][64 + tx * 4];
            float a[8] = {a0.x, a0.y, a0.z, a0.w, a1.x, a1.y, a1.z, a1.w};
            float b[8] = {b0.x, b0.y, b0.z, b0.w, b1.x, b1.y, b1.z, b1.w};
#pragma unroll
            for (int i = 0; i < 8; i++)
#pragma unroll
                for (int j = 0; j < 8; j++)
                    acc[i][j] += a[i] * b[j];
        }
        __syncthreads();
    }
    const int rbase[2] = {bm + ty * 4, bm + 64 + ty * 4};
    const int cbase[2] = {bn + tx * 4, bn + 64 + tx * 4};
#pragma unroll
    for (int jh = 0; jh < 2; jh++) {
        const int col = cbase[jh];
        float4 bv = *(const float4*)&bias[col];
#pragma unroll
        for (int ih = 0; ih < 2; ih++) {
#pragma unroll
            for (int i = 0; i < 4; i++) {
                const int row = rbase[ih] + i;
                float4 v;
                v.x = acc[ih * 4 + i][jh * 4 + 0] + bv.x;
                v.y = acc[ih * 4 + i][jh * 4 + 1] + bv.y;
                v.z = acc[ih * 4 + i][jh * 4 + 2] + bv.z;
                v.w = acc[ih * 4 + i][jh * 4 + 3] + bv.w;
                v.x = v.x > 0.f ? v.x : 0.f;
                v.y = v.y > 0.f ? v.y : 0.f;
                v.z = v.z > 0.f ? v.z : 0.f;
                v.w = v.w > 0.f ? v.w : 0.f;
                __nv_bfloat162 p0 = __floats2bfloat162_rn(v.x, v.y);
                __nv_bfloat162 p1 = __floats2bfloat162_rn(v.z, v.w);
                uint2 pk; pk.x = *(uint32_t*)&p0; pk.y = *(uint32_t*)&p1;
                *(uint2*)&C[(size_t)row * N + col] = pk;
            }
        }
    }
}

// ===========================================================================
// interact5 (round-13 champion): warp-independent, register-batched gather.
// ===========================================================================
#define IFE 136
#define INTERACT_SMEM (8 * 32 * IFE * 2)      // 69632

__global__ __launch_bounds__(256, 2)
void interact5(const __nv_bfloat16* __restrict__ bottom,
               const int* __restrict__ cat,
               const float* __restrict__ emb,
               __nv_bfloat16* __restrict__ x) {
    extern __shared__ __nv_bfloat16 ism[];
    const int warp = threadIdx.x >> 5, lane = threadIdx.x & 31;
    const int b = blockIdx.x * 8 + warp;
    __nv_bfloat16* fs = ism + (size_t)warp * 32 * IFE;

    int ci = 0;
    if (lane < NUM_CAT) ci = cat[(size_t)lane * BATCH + b];

    *(uint2*)(fs + lane * 4) = *(const uint2*)(bottom + (size_t)b * 128 + lane * 4);

    float4 v[13];
#pragma unroll
    for (int h = 0; h < 2; h++) {
#pragma unroll
        for (int r = 0; r < 13; r++) {
            const int tb = h * 13 + r;
            const int idx = __shfl_sync(0xffffffffu, ci, tb);
            v[r] = *(const float4*)(emb + ((size_t)tb * TABLE_SIZE + idx) * 128 + lane * 4);
        }
#pragma unroll
        for (int r = 0; r < 13; r++) {
            const int row = h * 13 + r + 1;
            __nv_bfloat162 p0 = __floats2bfloat162_rn(v[r].x, v[r].y);
            __nv_bfloat162 p1 = __floats2bfloat162_rn(v[r].z, v[r].w);
            uint2 pk; pk.x = *(uint32_t*)&p0; pk.y = *(uint32_t*)&p1;
            *(uint2*)(fs + (size_t)row * IFE + lane * 4) = pk;
        }
    }

    {
        uint2 z; z.x = 0u; z.y = 0u;
        for (int i = lane; i < 5 * IFE / 4; i += 32)
            *(uint2*)(fs + 27 * IFE + i * 4) = z;
    }
    __syncwarp();

    wmma::fragment<wmma::accumulator, 16, 16, 16, float> g00, g10, g11;
    wmma::fill_fragment(g00, 0.0f);
    wmma::fill_fragment(g10, 0.0f);
    wmma::fill_fragment(g11, 0.0f);
#pragma unroll
    for (int kk = 0; kk < 128; kk += 16) {
        wmma::fragment<wmma::matrix_a, 16, 16, 16, __nv_bfloat16, wmma::row_major> a0, a1;
        wmma::fragment<wmma::matrix_b, 16, 16, 16, __nv_bfloat16, wmma::col_major> b0, b1;
        wmma::load_matrix_sync(a0, fs + kk, IFE);
        wmma::load_matrix_sync(a1, fs + 16 * IFE + kk, IFE);
        wmma::load_matrix_sync(b0, fs + kk, IFE);
        wmma::load_matrix_sync(b1, fs + 16 * IFE + kk, IFE);
        wmma::mma_sync(g00, a0, b0, g00);
        wmma::mma_sync(g10, a1, b0, g10);
        wmma::mma_sync(g11, a1, b1, g11);
    }

    float* gs = (float*)fs;
    wmma::store_matrix_sync(gs, g00, 34, wmma::mem_row_major);
    wmma::store_matrix_sync(gs + 16 * 34, g10, 34, wmma::mem_row_major);
    wmma::store_matrix_sync(gs + 16 * 34 + 16, g11, 34, wmma::mem_row_major);
    __syncwarp();

    __nv_bfloat16* xb = x + (size_t)b * TOP_IN_P;
    *(uint2*)(xb + lane * 4) = *(const uint2*)(bottom + (size_t)b * 128 + lane * 4);
    if (lane < 8) {
        uint2 z; z.x = 0u; z.y = 0u;
        *(uint2*)(xb + 480 + lane * 4) = z;
    } else if (lane == 8) {
        xb[TOP_IN - 1] = __float2bfloat16(0.f);
    }
    for (int p = lane; p < 351; p += 32) {
        int r = (int)((1.0f + sqrtf(8.0f * (float)p + 1.0f)) * 0.5f);
        if (r * (r - 1) / 2 > p) r--;
        if ((r + 1) * r / 2 <= p) r++;
        const int c = p - r * (r - 1) / 2;
        xb[128 + p] = __float2bfloat16(gs[r * 34 + c]);
    }
}

// ===========================================================================
// Final layer: sigmoid(dot(t4_bf16, w5) + b5). Warp per sample.
// ===========================================================================
__global__ __launch_bounds__(256)
void final_layer(const __nv_bfloat16* __restrict__ A,
                 const float* __restrict__ w5,
                 const float* __restrict__ b5, float* __restrict__ out) {
    const int gwarp = (blockIdx.x * blockDim.x + threadIdx.x) >> 5;
    const int lane = threadIdx.x & 31;
    if (gwarp >= BATCH) return;
    uint4 raw = *(const uint4*)(A + (size_t)gwarp * 256 + lane * 8);
    const float4* w4 = (const float4*)(w5 + lane * 8);
    float4 w0 = w4[0], w1 = w4[1];
    __nv_bfloat162 p0 = *(__nv_bfloat162*)&raw.x;
    __nv_bfloat162 p1 = *(__nv_bfloat162*)&raw.y;
    __nv_bfloat162 p2 = *(__nv_bfloat162*)&raw.z;
    __nv_bfloat162 p3 = *(__nv_bfloat162*)&raw.w;
    float s = __bfloat162float(p0.x) * w0.x + __bfloat162float(p0.y) * w0.y +
              __bfloat162float(p1.x) * w0.z + __bfloat162float(p1.y) * w0.w +
              __bfloat162float(p2.x) * w1.x + __bfloat162float(p2.y) * w1.y +
              __bfloat162float(p3.x) * w1.z + __bfloat162float(p3.y) * w1.w;
#pragma unroll
    for (int o = 16; o; o >>= 1) s += __shfl_xor_sync(0xffffffffu, s, o);
    if (lane == 0) out[gwarp] = 1.f / (1.f + expf(-(s + b5[0])));
}

// ===========================================================================
extern "C" void kernel_launch(void* const* d_in, const int* in_sizes, int n_in,
                              void* d_out, int out_size) {
    const float* num = (const float*)d_in[0];
    const int*   cat = (const int*)  d_in[1];
    const float* emb = (const float*)d_in[2];
    const float* bw1 = (const float*)d_in[3];
    const float* bb1 = (const float*)d_in[4];
    const float* bw2 = (const float*)d_in[5];
    const float* bb2 = (const float*)d_in[6];
    const float* bw3 = (const float*)d_in[7];
    const float* bb3 = (const float*)d_in[8];
    const float* tw1 = (const float*)d_in[9];
    const float* tb1 = (const float*)d_in[10];
    const float* tw2 = (const float*)d_in[11];
    const float* tb2 = (const float*)d_in[12];
    const float* tw3 = (const float*)d_in[13];
    const float* tb3 = (const float*)d_in[14];
    const float* tw4 = (const float*)d_in[15];
    const float* tb4 = (const float*)d_in[16];
    const float* tw5 = (const float*)d_in[17];
    const float* tb5 = (const float*)d_in[18];
    float* out = (float*)d_out;

    __nv_bfloat16 *h1, *h2, *bot, *x, *t1, *t2, *t3, *t4;
    __nv_bfloat16 *bw2r, *bw3r, *tw1r, *tw2r, *tw3r, *tw4r;
    cudaGetSymbolAddress((void**)&h1,  g_h1);
    cudaGetSymbolAddress((void**)&h2,  g_h2);
    cudaGetSymbolAddress((void**)&bot, g_bot);
    cudaGetSymbolAddress((void**)&x,   g_x);
    cudaGetSymbolAddress((void**)&t1,  g_t1);
    cudaGetSymbolAddress((void**)&t2,  g_t2);
    cudaGetSymbolAddress((void**)&t3,  g_t3);
    cudaGetSymbolAddress((void**)&t4,  g_t4);
    cudaGetSymbolAddress((void**)&bw2r, g_bw2r);
    cudaGetSymbolAddress((void**)&bw3r, g_bw3r);
    cudaGetSymbolAddress((void**)&tw1r, g_tw1r);
    cudaGetSymbolAddress((void**)&tw2r, g_tw2r);
    cudaGetSymbolAddress((void**)&tw3r, g_tw3r);
    cudaGetSymbolAddress((void**)&tw4r, g_tw4r);

    cudaFuncSetAttribute(bf16_gemm, cudaFuncAttributeMaxDynamicSharedMemorySize, GEMM_SMEM);
    cudaFuncSetAttribute(interact5, cudaFuncAttributeMaxDynamicSharedMemorySize, INTERACT_SMEM);

    const int MB = BATCH / 128;  // 128

    // launch 1: L1 SGEMM + weight rounding (fused)
    l1_and_round<<<dim3(4, MB + RB_Y), 256>>>(num, bw1, bb1, h1,
                                              bw2, bw3, tw1, tw2, tw3, tw4,
                                              bw2r, bw3r, tw1r, tw2r, tw3r, tw4r);

    // launches 2-3: bottom MLP
    bf16_gemm<<<dim3(2, MB), 128, GEMM_SMEM>>>(h1, bw2r, bb2, h2, 256, 512);
    bf16_gemm<<<dim3(1, MB), 128, GEMM_SMEM>>>(h2, bw3r, bb3, bot, 128, 256);

    // launch 4 (profiled): interaction
    interact5<<<BATCH / 8, 256, INTERACT_SMEM>>>(bot, cat, emb, x);

    // top MLP
    bf16_gemm<<<dim3(8, MB), 128, GEMM_SMEM>>>(x,  tw1r, tb1, t1, 1024, TOP_IN_P);
    bf16_gemm<<<dim3(8, MB), 128, GEMM_SMEM>>>(t1, tw2r, tb2, t2, 1024, 1024);
    bf16_gemm<<<dim3(4, MB), 128, GEMM_SMEM>>>(t2, tw3r, tb3, t3, 512, 1024);
    bf16_gemm<<<dim3(2, MB), 128, GEMM_SMEM>>>(t3, tw4r, tb4, t4, 256, 512);

    // final dot + sigmoid
    final_layer<<<(BATCH * 32 + 255) / 256, 256>>>(t4, tw5, tb5, out);
}

// round 16
// speedup vs baseline: 1.0243x; 1.0005x over previous
#include <cuda_runtime.h>
#include <cuda_bf16.h>
#include <mma.h>
#include <math.h>
#include <stdint.h>

using namespace nvcuda;

// ===========================================================================
// DLRM forward. bf16 wmma GEMMs (CTA 128x128, BK=32, 4-stage, 4 warps x
// 64x64, 2 CTAs/SM) + cp.async-gathered bf16-gram interaction.
// ===========================================================================

#define BATCH      16384
#define EMB_DIM    128
#define TABLE_SIZE 100000
#define NUM_CAT    26
#define NUM_FEATS  27
#define TOP_IN     480
#define TOP_IN_P   512

// ------------------------- scratch (device globals) ------------------------
__device__ __nv_bfloat16 g_h1[BATCH * 512];
__device__ __nv_bfloat16 g_h2[BATCH * 256];
__device__ __nv_bfloat16 g_bot[BATCH * 128];
__device__ __nv_bfloat16 g_x [BATCH * TOP_IN_P];
__device__ __nv_bfloat16 g_t1[BATCH * 1024];
__device__ __nv_bfloat16 g_t2[BATCH * 1024];
__device__ __nv_bfloat16 g_t3[BATCH * 512];
__device__ __nv_bfloat16 g_t4[BATCH * 256];
__device__ __nv_bfloat16 g_bw2r[256 * 512];
__device__ __nv_bfloat16 g_bw3r[128 * 256];
__device__ __nv_bfloat16 g_tw1r[1024 * TOP_IN_P];
__device__ __nv_bfloat16 g_tw2r[1024 * 1024];
__device__ __nv_bfloat16 g_tw3r[512 * 1024];
__device__ __nv_bfloat16 g_tw4r[256 * 512];

// ------------------------------ helpers ------------------------------------
__device__ __forceinline__ uint32_t smem_u32(const void* p) {
    return (uint32_t)__cvta_generic_to_shared(p);
}
#define CP_ASYNC16(dst, src) \
    asm volatile("cp.async.cg.shared.global [%0], [%1], 16;" :: "r"(dst), "l"(src))
__device__ __forceinline__ void cp_commit() { asm volatile("cp.async.commit_group;"); }
__device__ __forceinline__ void cp_wait_allow(int n) {
    if (n <= 0)      asm volatile("cp.async.wait_group 0;");
    else if (n == 1) asm volatile("cp.async.wait_group 1;");
    else             asm volatile("cp.async.wait_group 2;");
}

// ===========================================================================
// bf16 wmma GEMM (round-13 champion): CTA 128x128, BK=32, 4 stages,
// 4 warps x 64x64.
// ===========================================================================
#define LDM 40
#define STAGE_ELEMS (2 * 128 * LDM)
#define STAGE_BYTES (STAGE_ELEMS * 2)        // 20480
#define GEMM_SMEM   (4 * STAGE_BYTES)        // 81920

__global__ __launch_bounds__(128, 2)
void bf16_gemm(const __nv_bfloat16* __restrict__ A,
               const __nv_bfloat16* __restrict__ W,
               const float* __restrict__ bias,
               __nv_bfloat16* __restrict__ C,
               int N, int K) {
    extern __shared__ __nv_bfloat16 smem[];
    const int tid = threadIdx.x;
    const int warp = tid >> 5;
    const int bm = blockIdx.y * 128;
    const int bn = blockIdx.x * 128;
    const int wm = warp >> 1;
    const int wn = warp & 1;
    const uint32_t sb = smem_u32(smem);

    wmma::fragment<wmma::accumulator, 16, 16, 16, float> cf[4][4];
#pragma unroll
    for (int i = 0; i < 4; i++)
#pragma unroll
        for (int j = 0; j < 4; j++) wmma::fill_fragment(cf[i][j], 0.0f);

    const int T = K / 32;

    auto load_stage = [&](int t) {
        const int s = t & 3;
        const int k0 = t * 32;
        const uint32_t abase = sb + (uint32_t)s * STAGE_BYTES;
        const uint32_t bbase = abase + 128u * LDM * 2u;
#pragma unroll
        for (int i = 0; i < 4; i++) {
            int idx = tid + i * 128;
            int r = idx >> 2, c = idx & 3;
            CP_ASYNC16(abase + (uint32_t)(r * LDM + c * 8) * 2u,
                       A + (size_t)(bm + r) * K + k0 + c * 8);
        }
#pragma unroll
        for (int i = 0; i < 4; i++) {
            int idx = tid + i * 128;
            int r = idx >> 2, c = idx & 3;
            CP_ASYNC16(bbase + (uint32_t)(r * LDM + c * 8) * 2u,
                       W + (size_t)(bn + r) * K + k0 + c * 8);
        }
        cp_commit();
    };

    const int pre = T < 3 ? T : 3;
    for (int s = 0; s < pre; s++) load_stage(s);

    for (int t = 0; t < T; t++) {
        int allow = T - 1 - t; if (allow > 2) allow = 2;
        cp_wait_allow(allow);
        __syncthreads();
        if (t + 3 < T) load_stage(t + 3);

        const __nv_bfloat16* a = smem + (size_t)(t & 3) * STAGE_ELEMS;
        const __nv_bfloat16* b = a + 128 * LDM;
#pragma unroll
        for (int kk = 0; kk < 32; kk += 16) {
            wmma::fragment<wmma::matrix_a, 16, 16, 16, __nv_bfloat16, wmma::row_major> af[4];
            wmma::fragment<wmma::matrix_b, 16, 16, 16, __nv_bfloat16, wmma::col_major> bf[4];
#pragma unroll
            for (int i = 0; i < 4; i++)
                wmma::load_matrix_sync(af[i], a + (wm * 64 + i * 16) * LDM + kk, LDM);
#pragma unroll
            for (int j = 0; j < 4; j++)
                wmma::load_matrix_sync(bf[j], b + (wn * 64 + j * 16) * LDM + kk, LDM);
#pragma unroll
            for (int i = 0; i < 4; i++)
#pragma unroll
                for (int j = 0; j < 4; j++)
                    wmma::mma_sync(cf[i][j], af[i], bf[j], cf[i][j]);
        }
    }
    __syncthreads();

    // epilogue: fragments -> smem(fp32 128x132) -> bf16 gmem
    float* cs = (float*)smem;
#pragma unroll
    for (int i = 0; i < 4; i++)
#pragma unroll
        for (int j = 0; j < 4; j++)
            wmma::store_matrix_sync(cs + (size_t)(wm * 64 + i * 16) * 132 + wn * 64 + j * 16,
                                    cf[i][j], 132, wmma::mem_row_major);
    __syncthreads();

    {
        const int row = tid;
        const float* src = cs + (size_t)row * 132;
        __nv_bfloat16* dst = C + (size_t)(bm + row) * N + bn;
#pragma unroll
        for (int q = 0; q < 8; q++) {
            float4 v  = *(const float4*)(src + q * 16);
            float4 v1 = *(const float4*)(src + q * 16 + 4);
            float4 v2 = *(const float4*)(src + q * 16 + 8);
            float4 v3 = *(const float4*)(src + q * 16 + 12);
            float4 b0 = *(const float4*)(bias + bn + q * 16);
            float4 b1 = *(const float4*)(bias + bn + q * 16 + 4);
            float4 b2 = *(const float4*)(bias + bn + q * 16 + 8);
            float4 b3 = *(const float4*)(bias + bn + q * 16 + 12);
            v.x += b0.x;  v.y += b0.y;  v.z += b0.z;  v.w += b0.w;
            v1.x += b1.x; v1.y += b1.y; v1.z += b1.z; v1.w += b1.w;
            v2.x += b2.x; v2.y += b2.y; v2.z += b2.z; v2.w += b2.w;
            v3.x += b3.x; v3.y += b3.y; v3.z += b3.z; v3.w += b3.w;
            v.x = v.x > 0.f ? v.x : 0.f;   v.y = v.y > 0.f ? v.y : 0.f;
            v.z = v.z > 0.f ? v.z : 0.f;   v.w = v.w > 0.f ? v.w : 0.f;
            v1.x = v1.x > 0.f ? v1.x : 0.f; v1.y = v1.y > 0.f ? v1.y : 0.f;
            v1.z = v1.z > 0.f ? v1.z : 0.f; v1.w = v1.w > 0.f ? v1.w : 0.f;
            v2.x = v2.x > 0.f ? v2.x : 0.f; v2.y = v2.y > 0.f ? v2.y : 0.f;
            v2.z = v2.z > 0.f ? v2.z : 0.f; v2.w = v2.w > 0.f ? v2.w : 0.f;
            v3.x = v3.x > 0.f ? v3.x : 0.f; v3.y = v3.y > 0.f ? v3.y : 0.f;
            v3.z = v3.z > 0.f ? v3.z : 0.f; v3.w = v3.w > 0.f ? v3.w : 0.f;
            __nv_bfloat162 p0 = __floats2bfloat162_rn(v.x, v.y);
            __nv_bfloat162 p1 = __floats2bfloat162_rn(v.z, v.w);
            __nv_bfloat162 p2 = __floats2bfloat162_rn(v1.x, v1.y);
            __nv_bfloat162 p3 = __floats2bfloat162_rn(v1.z, v1.w);
            __nv_bfloat162 p4 = __floats2bfloat162_rn(v2.x, v2.y);
            __nv_bfloat162 p5 = __floats2bfloat162_rn(v2.z, v2.w);
            __nv_bfloat162 p6 = __floats2bfloat162_rn(v3.x, v3.y);
            __nv_bfloat162 p7 = __floats2bfloat162_rn(v3.z, v3.w);
            uint4 pk0, pk1;
            pk0.x = *(uint32_t*)&p0; pk0.y = *(uint32_t*)&p1;
            pk0.z = *(uint32_t*)&p2; pk0.w = *(uint32_t*)&p3;
            pk1.x = *(uint32_t*)&p4; pk1.y = *(uint32_t*)&p5;
            pk1.z = *(uint32_t*)&p6; pk1.w = *(uint32_t*)&p7;
            *(uint4*)(dst + q * 16)     = pk0;
            *(uint4*)(dst + q * 16 + 8) = pk1;
        }
    }
}

// ===========================================================================
// Fused L1 SGEMM (K=13) + weight rounding (blockIdx.y >= 128).
// ===========================================================================
#define RW_N0 131072
#define RW_N1 32768
#define RW_N2 (1024 * TOP_IN_P)
#define RW_N3 1048576
#define RW_N4 524288
#define RW_N5 131072
#define RW_TOTAL (RW_N0 + RW_N1 + RW_N2 + RW_N3 + RW_N4 + RW_N5)
#define RB_Y 128

__global__ __launch_bounds__(256, 2)
void l1_and_round(const float* __restrict__ A, const float* __restrict__ W,
                  const float* __restrict__ bias, __nv_bfloat16* __restrict__ C,
                  const float* __restrict__ bw2, const float* __restrict__ bw3,
                  const float* __restrict__ tw1, const float* __restrict__ tw2,
                  const float* __restrict__ tw3, const float* __restrict__ tw4,
                  __nv_bfloat16* __restrict__ d0, __nv_bfloat16* __restrict__ d1,
                  __nv_bfloat16* __restrict__ d2, __nv_bfloat16* __restrict__ d3,
                  __nv_bfloat16* __restrict__ d4, __nv_bfloat16* __restrict__ d5) {
    const int tid = threadIdx.x;

    if (blockIdx.y >= BATCH / 128) {
        const int nrb = 4 * RB_Y;
        const int rb = (blockIdx.y - BATCH / 128) * 4 + blockIdx.x;
        const int stride = nrb * 256;
        for (int i = rb * 256 + tid; i < RW_TOTAL; i += stride) {
            int j = i;
            if (j < RW_N0) { d0[j] = __float2bfloat16(bw2[j]); continue; }
            j -= RW_N0;
            if (j < RW_N1) { d1[j] = __float2bfloat16(bw3[j]); continue; }
            j -= RW_N1;
            if (j < RW_N2) {
                int n = j / TOP_IN_P, k = j % TOP_IN_P;
                d2[j] = (k < TOP_IN) ? __float2bfloat16(tw1[n * TOP_IN + k])
                                     : __float2bfloat16(0.f);
                continue;
            }
            j -= RW_N2;
            if (j < RW_N3) { d3[j] = __float2bfloat16(tw2[j]); continue; }
            j -= RW_N3;
            if (j < RW_N4) { d4[j] = __float2bfloat16(tw3[j]); continue; }
            j -= RW_N4;
            d5[j] = __float2bfloat16(tw4[j]);
        }
        return;
    }

    const int N = 512, K = 13;
    __shared__ float As[8][132];
    __shared__ float Bs[8][132];
    const int bm = blockIdx.y * 128, bn = blockIdx.x * 128;
    const int tx = tid & 15, ty = tid >> 4;
    const int lk = tid & 7, lr = tid >> 3;

    float acc[8][8];
#pragma unroll
    for (int i = 0; i < 8; i++)
#pragma unroll
        for (int j = 0; j < 8; j++) acc[i][j] = 0.f;

    for (int k0 = 0; k0 < K; k0 += 8) {
        const int kk = k0 + lk;
        const bool kv = (kk < K);
#pragma unroll
        for (int p = 0; p < 4; p++) {
            const int row = lr + p * 32;
            As[lk][row] = kv ? A[(size_t)(bm + row) * K + kk] : 0.f;
            Bs[lk][row] = kv ? W[(size_t)(bn + row) * K + kk] : 0.f;
        }
        __syncthreads();
#pragma unroll
        for (int k = 0; k < 8; k++) {
            float4 a0 = *(const float4*)&As[k][ty * 4];
            float4 a1 = *(const float4*)&As[k][64 + ty * 4];
            float4 b0 = *(const float4*)&Bs[k][tx * 4];
            float4 b1 = *(const float4*)&Bs[k][64 + tx * 4];
            float a[8] = {a0.x, a0.y, a0.z, a0.w, a1.x, a1.y, a1.z, a1.w};
            float b[8] = {b0.x, b0.y, b0.z, b0.w, b1.x, b1.y, b1.z, b1.w};
#pragma unroll
            for (int i = 0; i < 8; i++)
#pragma unroll
                for (int j = 0; j < 8; j++)
                    acc[i][j] += a[i] * b[j];
        }
        __syncthreads();
    }
    const int rbase[2] = {bm + ty * 4, bm + 64 + ty * 4};
    const int cbase[2] = {bn + tx * 4, bn + 64 + tx * 4};
#pragma unroll
    for (int jh = 0; jh < 2; jh++) {
        const int col = cbase[jh];
        float4 bv = *(const float4*)&bias[col];
#pragma unroll
        for (int ih = 0; ih < 2; ih++) {
#pragma unroll
            for (int i = 0; i < 4; i++) {
                const int row = rbase[ih] + i;
                float4 v;
                v.x = acc[ih * 4 + i][jh * 4 + 0] + bv.x;
                v.y = acc[ih * 4 + i][jh * 4 + 1] + bv.y;
                v.z = acc[ih * 4 + i][jh * 4 + 2] + bv.z;
                v.w = acc[ih * 4 + i][jh * 4 + 3] + bv.w;
                v.x = v.x > 0.f ? v.x : 0.f;
                v.y = v.y > 0.f ? v.y : 0.f;
                v.z = v.z > 0.f ? v.z : 0.f;
                v.w = v.w > 0.f ? v.w : 0.f;
                __nv_bfloat162 p0 = __floats2bfloat162_rn(v.x, v.y);
                __nv_bfloat162 p1 = __floats2bfloat162_rn(v.z, v.w);
                uint2 pk; pk.x = *(uint32_t*)&p0; pk.y = *(uint32_t*)&p1;
                *(uint2*)&C[(size_t)row * N + col] = pk;
            }
        }
    }
}

// ===========================================================================
// interact7: cp.async gather into fp32 smem, IN-PLACE fp32->bf16 convert,
// bf16 3-tile gram (identical math to interact5). 128 thr = 4 warps =
// 4 samples/CTA, 3 CTAs/SM = 12 warps. No CTA barriers.
// Alias proof: bf16 row r = bytes [272r, 272r+256); fp32 row r = [528r,
// 528r+512). 272r+256 <= 528r for all r>=1 -> convert is in-place safe.
// ===========================================================================
#define IF32 132                               // fp32 staging row stride
#define IFE  136                               // bf16 feats row stride
#define INTERACT_SMEM (4 * 32 * IF32 * 4)      // 67584

__global__ __launch_bounds__(128, 3)
void interact7(const __nv_bfloat16* __restrict__ bottom,
               const int* __restrict__ cat,
               const float* __restrict__ emb,
               __nv_bfloat16* __restrict__ x) {
    extern __shared__ float fsm[];
    const int warp = threadIdx.x >> 5, lane = threadIdx.x & 31;
    const int b = blockIdx.x * 4 + warp;
    float* fp = fsm + (size_t)warp * 32 * IF32;      // fp32 staging
    __nv_bfloat16* fs = (__nv_bfloat16*)fp;          // bf16 feats (in place)
    const uint32_t fpb = smem_u32(fp);

    int ci = 0;
    if (lane < NUM_CAT) ci = cat[(size_t)lane * BATCH + b];

    // rows 1..26 via cp.async: 26 x 512 B per warp, one group, all in flight
#pragma unroll
    for (int r = 1; r <= 26; r++) {
        const int idx = __shfl_sync(0xffffffffu, ci, r - 1);
        CP_ASYNC16(fpb + (uint32_t)(r * IF32 + lane * 4) * 4u,
                   emb + ((size_t)(r - 1) * TABLE_SIZE + idx) * 128 + lane * 4);
    }
    cp_commit();

    // row 0 (bottom, already bf16): bytes [0,256) -- below all cp targets
    *(uint2*)(fs + lane * 4) = *(const uint2*)(bottom + (size_t)b * 128 + lane * 4);

    cp_wait_allow(0);
    __syncwarp();

    // in-place convert rows 1..26: fp32 [528r..) -> bf16 [272r..)
#pragma unroll
    for (int r = 1; r <= 26; r++) {
        float4 v = *(const float4*)(fp + r * IF32 + lane * 4);
        __nv_bfloat162 p0 = __floats2bfloat162_rn(v.x, v.y);
        __nv_bfloat162 p1 = __floats2bfloat162_rn(v.z, v.w);
        uint2 pk; pk.x = *(uint32_t*)&p0; pk.y = *(uint32_t*)&p1;
        *(uint2*)(fs + (size_t)r * IFE + lane * 4) = pk;
    }
    __syncwarp();

    // zero bf16 rows 27..31: 5*IFE = 680 bf16 = 170 uint2
    {
        uint2 z; z.x = 0u; z.y = 0u;
        for (int i = lane; i < 5 * IFE / 4; i += 32)
            *(uint2*)(fs + 27 * IFE + i * 4) = z;
    }
    __syncwarp();

    // gram: G = F F^T, bf16, 3 tiles
    wmma::fragment<wmma::accumulator, 16, 16, 16, float> g00, g10, g11;
    wmma::fill_fragment(g00, 0.0f);
    wmma::fill_fragment(g10, 0.0f);
    wmma::fill_fragment(g11, 0.0f);
#pragma unroll
    for (int kk = 0; kk < 128; kk += 16) {
        wmma::fragment<wmma::matrix_a, 16, 16, 16, __nv_bfloat16, wmma::row_major> a0, a1;
        wmma::fragment<wmma::matrix_b, 16, 16, 16, __nv_bfloat16, wmma::col_major> b0, b1;
        wmma::load_matrix_sync(a0, fs + kk, IFE);
        wmma::load_matrix_sync(a1, fs + 16 * IFE + kk, IFE);
        wmma::load_matrix_sync(b0, fs + kk, IFE);
        wmma::load_matrix_sync(b1, fs + 16 * IFE + kk, IFE);
        wmma::mma_sync(g00, a0, b0, g00);
        wmma::mma_sync(g10, a1, b0, g10);
        wmma::mma_sync(g11, a1, b1, g11);
    }

    // stage G into this warp's own patch (32*34 f32 = 4352 B)
    float* gs = fp;
    wmma::store_matrix_sync(gs, g00, 34, wmma::mem_row_major);
    wmma::store_matrix_sync(gs + 16 * 34, g10, 34, wmma::mem_row_major);
    wmma::store_matrix_sync(gs + 16 * 34 + 16, g11, 34, wmma::mem_row_major);
    __syncwarp();

    // outputs
    __nv_bfloat16* xb = x + (size_t)b * TOP_IN_P;
    *(uint2*)(xb + lane * 4) = *(const uint2*)(bottom + (size_t)b * 128 + lane * 4);
    if (lane < 8) {
        uint2 z; z.x = 0u; z.y = 0u;
        *(uint2*)(xb + 480 + lane * 4) = z;
    } else if (lane == 8) {
        xb[TOP_IN - 1] = __float2bfloat16(0.f);
    }
    for (int p = lane; p < 351; p += 32) {
        int r = (int)((1.0f + sqrtf(8.0f * (float)p + 1.0f)) * 0.5f);
        if (r * (r - 1) / 2 > p) r--;
        if ((r + 1) * r / 2 <= p) r++;
        const int c = p - r * (r - 1) / 2;
        xb[128 + p] = __float2bfloat16(gs[r * 34 + c]);
    }
}

// ===========================================================================
// Final layer: sigmoid(dot(t4_bf16, w5) + b5). Warp per sample.
// ===========================================================================
__global__ __launch_bounds__(256)
void final_layer(const __nv_bfloat16* __restrict__ A,
                 const float* __restrict__ w5,
                 const float* __restrict__ b5, float* __restrict__ out) {
    const int gwarp = (blockIdx.x * blockDim.x + threadIdx.x) >> 5;
    const int lane = threadIdx.x & 31;
    if (gwarp >= BATCH) return;
    uint4 raw = *(const uint4*)(A + (size_t)gwarp * 256 + lane * 8);
    const float4* w4 = (const float4*)(w5 + lane * 8);
    float4 w0 = w4[0], w1 = w4[1];
    __nv_bfloat162 p0 = *(__nv_bfloat162*)&raw.x;
    __nv_bfloat162 p1 = *(__nv_bfloat162*)&raw.y;
    __nv_bfloat162 p2 = *(__nv_bfloat162*)&raw.z;
    __nv_bfloat162 p3 = *(__nv_bfloat162*)&raw.w;
    float s = __bfloat162float(p0.x) * w0.x + __bfloat162float(p0.y) * w0.y +
              __bfloat162float(p1.x) * w0.z + __bfloat162float(p1.y) * w0.w +
              __bfloat162float(p2.x) * w1.x + __bfloat162float(p2.y) * w1.y +
              __bfloat162float(p3.x) * w1.z + __bfloat162float(p3.y) * w1.w;
#pragma unroll
    for (int o = 16; o; o >>= 1) s += __shfl_xor_sync(0xffffffffu, s, o);
    if (lane == 0) out[gwarp] = 1.f / (1.f + expf(-(s + b5[0])));
}

// ===========================================================================
extern "C" void kernel_launch(void* const* d_in, const int* in_sizes, int n_in,
                              void* d_out, int out_size) {
    const float* num = (const float*)d_in[0];
    const int*   cat = (const int*)  d_in[1];
    const float* emb = (const float*)d_in[2];
    const float* bw1 = (const float*)d_in[3];
    const float* bb1 = (const float*)d_in[4];
    const float* bw2 = (const float*)d_in[5];
    const float* bb2 = (const float*)d_in[6];
    const float* bw3 = (const float*)d_in[7];
    const float* bb3 = (const float*)d_in[8];
    const float* tw1 = (const float*)d_in[9];
    const float* tb1 = (const float*)d_in[10];
    const float* tw2 = (const float*)d_in[11];
    const float* tb2 = (const float*)d_in[12];
    const float* tw3 = (const float*)d_in[13];
    const float* tb3 = (const float*)d_in[14];
    const float* tw4 = (const float*)d_in[15];
    const float* tb4 = (const float*)d_in[16];
    const float* tw5 = (const float*)d_in[17];
    const float* tb5 = (const float*)d_in[18];
    float* out = (float*)d_out;

    __nv_bfloat16 *h1, *h2, *bot, *x, *t1, *t2, *t3, *t4;
    __nv_bfloat16 *bw2r, *bw3r, *tw1r, *tw2r, *tw3r, *tw4r;
    cudaGetSymbolAddress((void**)&h1,  g_h1);
    cudaGetSymbolAddress((void**)&h2,  g_h2);
    cudaGetSymbolAddress((void**)&bot, g_bot);
    cudaGetSymbolAddress((void**)&x,   g_x);
    cudaGetSymbolAddress((void**)&t1,  g_t1);
    cudaGetSymbolAddress((void**)&t2,  g_t2);
    cudaGetSymbolAddress((void**)&t3,  g_t3);
    cudaGetSymbolAddress((void**)&t4,  g_t4);
    cudaGetSymbolAddress((void**)&bw2r, g_bw2r);
    cudaGetSymbolAddress((void**)&bw3r, g_bw3r);
    cudaGetSymbolAddress((void**)&tw1r, g_tw1r);
    cudaGetSymbolAddress((void**)&tw2r, g_tw2r);
    cudaGetSymbolAddress((void**)&tw3r, g_tw3r);
    cudaGetSymbolAddress((void**)&tw4r, g_tw4r);

    cudaFuncSetAttribute(bf16_gemm, cudaFuncAttributeMaxDynamicSharedMemorySize, GEMM_SMEM);
    cudaFuncSetAttribute(interact7, cudaFuncAttributeMaxDynamicSharedMemorySize, INTERACT_SMEM);

    const int MB = BATCH / 128;  // 128

    // launch 1: L1 SGEMM + weight rounding (fused)
    l1_and_round<<<dim3(4, MB + RB_Y), 256>>>(num, bw1, bb1, h1,
                                              bw2, bw3, tw1, tw2, tw3, tw4,
                                              bw2r, bw3r, tw1r, tw2r, tw3r, tw4r);

    // launches 2-3: bottom MLP
    bf16_gemm<<<dim3(2, MB), 128, GEMM_SMEM>>>(h1, bw2r, bb2, h2, 256, 512);
    bf16_gemm<<<dim3(1, MB), 128, GEMM_SMEM>>>(h2, bw3r, bb3, bot, 128, 256);

    // launch 4 (profiled): interaction
    interact7<<<BATCH / 4, 128, INTERACT_SMEM>>>(bot, cat, emb, x);

    // top MLP
    bf16_gemm<<<dim3(8, MB), 128, GEMM_SMEM>>>(x,  tw1r, tb1, t1, 1024, TOP_IN_P);
    bf16_gemm<<<dim3(8, MB), 128, GEMM_SMEM>>>(t1, tw2r, tb2, t2, 1024, 1024);
    bf16_gemm<<<dim3(4, MB), 128, GEMM_SMEM>>>(t2, tw3r, tb3, t3, 512, 1024);
    bf16_gemm<<<dim3(2, MB), 128, GEMM_SMEM>>>(t3, tw4r, tb4, t4, 256, 512);

    // final dot + sigmoid
    final_layer<<<(BATCH * 32 + 255) / 256, 256>>>(t4, tw5, tb5, out);
}

// round 17
// speedup vs baseline: 1.0402x; 1.0155x over previous
#include <cuda_runtime.h>
#include <cuda_bf16.h>
#include <mma.h>
#include <math.h>
#include <stdint.h>

using namespace nvcuda;

// ===========================================================================
// DLRM forward. bf16 wmma GEMMs: CTA 128x128, BK=32, 4-stage cp.async,
// 4 warps x 64x64 warp-tiles, 2 CTAs/SM. interact5 (register-batched gather).
// T1 runs unpadded K=480 (480 % 32 == 0).
// ===========================================================================

#define BATCH      16384
#define EMB_DIM    128
#define TABLE_SIZE 100000
#define NUM_CAT    26
#define NUM_FEATS  27
#define TOP_IN     480

// ------------------------- scratch (device globals) ------------------------
__device__ __nv_bfloat16 g_h1[BATCH * 512];
__device__ __nv_bfloat16 g_h2[BATCH * 256];
__device__ __nv_bfloat16 g_bot[BATCH * 128];
__device__ __nv_bfloat16 g_x [BATCH * TOP_IN];
__device__ __nv_bfloat16 g_t1[BATCH * 1024];
__device__ __nv_bfloat16 g_t2[BATCH * 1024];
__device__ __nv_bfloat16 g_t3[BATCH * 512];
__device__ __nv_bfloat16 g_t4[BATCH * 256];
__device__ __nv_bfloat16 g_bw2r[256 * 512];
__device__ __nv_bfloat16 g_bw3r[128 * 256];
__device__ __nv_bfloat16 g_tw1r[1024 * TOP_IN];
__device__ __nv_bfloat16 g_tw2r[1024 * 1024];
__device__ __nv_bfloat16 g_tw3r[512 * 1024];
__device__ __nv_bfloat16 g_tw4r[256 * 512];

// ------------------------------ helpers ------------------------------------
__device__ __forceinline__ uint32_t smem_u32(const void* p) {
    return (uint32_t)__cvta_generic_to_shared(p);
}
#define CP_ASYNC16(dst, src) \
    asm volatile("cp.async.cg.shared.global [%0], [%1], 16;" :: "r"(dst), "l"(src))
__device__ __forceinline__ void cp_commit() { asm volatile("cp.async.commit_group;"); }
__device__ __forceinline__ void cp_wait_allow(int n) {
    if (n <= 0)      asm volatile("cp.async.wait_group 0;");
    else if (n == 1) asm volatile("cp.async.wait_group 1;");
    else             asm volatile("cp.async.wait_group 2;");
}

// ===========================================================================
// bf16 wmma GEMM (champion): CTA 128x128, BK=32, 4 stages, 4 warps x 64x64.
// ===========================================================================
#define LDM 40
#define STAGE_ELEMS (2 * 128 * LDM)
#define STAGE_BYTES (STAGE_ELEMS * 2)        // 20480
#define GEMM_SMEM   (4 * STAGE_BYTES)        // 81920

__global__ __launch_bounds__(128, 2)
void bf16_gemm(const __nv_bfloat16* __restrict__ A,
               const __nv_bfloat16* __restrict__ W,
               const float* __restrict__ bias,
               __nv_bfloat16* __restrict__ C,
               int N, int K) {
    extern __shared__ __nv_bfloat16 smem[];
    const int tid = threadIdx.x;
    const int warp = tid >> 5;
    const int bm = blockIdx.y * 128;
    const int bn = blockIdx.x * 128;
    const int wm = warp >> 1;
    const int wn = warp & 1;
    const uint32_t sb = smem_u32(smem);

    wmma::fragment<wmma::accumulator, 16, 16, 16, float> cf[4][4];
#pragma unroll
    for (int i = 0; i < 4; i++)
#pragma unroll
        for (int j = 0; j < 4; j++) wmma::fill_fragment(cf[i][j], 0.0f);

    const int T = K / 32;

    auto load_stage = [&](int t) {
        const int s = t & 3;
        const int k0 = t * 32;
        const uint32_t abase = sb + (uint32_t)s * STAGE_BYTES;
        const uint32_t bbase = abase + 128u * LDM * 2u;
#pragma unroll
        for (int i = 0; i < 4; i++) {
            int idx = tid + i * 128;
            int r = idx >> 2, c = idx & 3;
            CP_ASYNC16(abase + (uint32_t)(r * LDM + c * 8) * 2u,
                       A + (size_t)(bm + r) * K + k0 + c * 8);
        }
#pragma unroll
        for (int i = 0; i < 4; i++) {
            int idx = tid + i * 128;
            int r = idx >> 2, c = idx & 3;
            CP_ASYNC16(bbase + (uint32_t)(r * LDM + c * 8) * 2u,
                       W + (size_t)(bn + r) * K + k0 + c * 8);
        }
        cp_commit();
    };

    const int pre = T < 3 ? T : 3;
    for (int s = 0; s < pre; s++) load_stage(s);

    for (int t = 0; t < T; t++) {
        int allow = T - 1 - t; if (allow > 2) allow = 2;
        cp_wait_allow(allow);
        __syncthreads();
        if (t + 3 < T) load_stage(t + 3);

        const __nv_bfloat16* a = smem + (size_t)(t & 3) * STAGE_ELEMS;
        const __nv_bfloat16* b = a + 128 * LDM;
#pragma unroll
        for (int kk = 0; kk < 32; kk += 16) {
            wmma::fragment<wmma::matrix_a, 16, 16, 16, __nv_bfloat16, wmma::row_major> af[4];
            wmma::fragment<wmma::matrix_b, 16, 16, 16, __nv_bfloat16, wmma::col_major> bf[4];
#pragma unroll
            for (int i = 0; i < 4; i++)
                wmma::load_matrix_sync(af[i], a + (wm * 64 + i * 16) * LDM + kk, LDM);
#pragma unroll
            for (int j = 0; j < 4; j++)
                wmma::load_matrix_sync(bf[j], b + (wn * 64 + j * 16) * LDM + kk, LDM);
#pragma unroll
            for (int i = 0; i < 4; i++)
#pragma unroll
                for (int j = 0; j < 4; j++)
                    wmma::mma_sync(cf[i][j], af[i], bf[j], cf[i][j]);
        }
    }
    __syncthreads();

    // epilogue: fragments -> smem(fp32 128x132) -> bf16 gmem
    float* cs = (float*)smem;
#pragma unroll
    for (int i = 0; i < 4; i++)
#pragma unroll
        for (int j = 0; j < 4; j++)
            wmma::store_matrix_sync(cs + (size_t)(wm * 64 + i * 16) * 132 + wn * 64 + j * 16,
                                    cf[i][j], 132, wmma::mem_row_major);
    __syncthreads();

    {
        const int row = tid;
        const float* src = cs + (size_t)row * 132;
        __nv_bfloat16* dst = C + (size_t)(bm + row) * N + bn;
#pragma unroll
        for (int q = 0; q < 8; q++) {
            float4 v  = *(const float4*)(src + q * 16);
            float4 v1 = *(const float4*)(src + q * 16 + 4);
            float4 v2 = *(const float4*)(src + q * 16 + 8);
            float4 v3 = *(const float4*)(src + q * 16 + 12);
            float4 b0 = *(const float4*)(bias + bn + q * 16);
            float4 b1 = *(const float4*)(bias + bn + q * 16 + 4);
            float4 b2 = *(const float4*)(bias + bn + q * 16 + 8);
            float4 b3 = *(const float4*)(bias + bn + q * 16 + 12);
            v.x += b0.x;  v.y += b0.y;  v.z += b0.z;  v.w += b0.w;
            v1.x += b1.x; v1.y += b1.y; v1.z += b1.z; v1.w += b1.w;
            v2.x += b2.x; v2.y += b2.y; v2.z += b2.z; v2.w += b2.w;
            v3.x += b3.x; v3.y += b3.y; v3.z += b3.z; v3.w += b3.w;
            v.x = v.x > 0.f ? v.x : 0.f;   v.y = v.y > 0.f ? v.y : 0.f;
            v.z = v.z > 0.f ? v.z : 0.f;   v.w = v.w > 0.f ? v.w : 0.f;
            v1.x = v1.x > 0.f ? v1.x : 0.f; v1.y = v1.y > 0.f ? v1.y : 0.f;
            v1.z = v1.z > 0.f ? v1.z : 0.f; v1.w = v1.w > 0.f ? v1.w : 0.f;
            v2.x = v2.x > 0.f ? v2.x : 0.f; v2.y = v2.y > 0.f ? v2.y : 0.f;
            v2.z = v2.z > 0.f ? v2.z : 0.f; v2.w = v2.w > 0.f ? v2.w : 0.f;
            v3.x = v3.x > 0.f ? v3.x : 0.f; v3.y = v3.y > 0.f ? v3.y : 0.f;
            v3.z = v3.z > 0.f ? v3.z : 0.f; v3.w = v3.w > 0.f ? v3.w : 0.f;
            __nv_bfloat162 p0 = __floats2bfloat162_rn(v.x, v.y);
            __nv_bfloat162 p1 = __floats2bfloat162_rn(v.z, v.w);
            __nv_bfloat162 p2 = __floats2bfloat162_rn(v1.x, v1.y);
            __nv_bfloat162 p3 = __floats2bfloat162_rn(v1.z, v1.w);
            __nv_bfloat162 p4 = __floats2bfloat162_rn(v2.x, v2.y);
            __nv_bfloat162 p5 = __floats2bfloat162_rn(v2.z, v2.w);
            __nv_bfloat162 p6 = __floats2bfloat162_rn(v3.x, v3.y);
            __nv_bfloat162 p7 = __floats2bfloat162_rn(v3.z, v3.w);
            uint4 pk0, pk1;
            pk0.x = *(uint32_t*)&p0; pk0.y = *(uint32_t*)&p1;
            pk0.z = *(uint32_t*)&p2; pk0.w = *(uint32_t*)&p3;
            pk1.x = *(uint32_t*)&p4; pk1.y = *(uint32_t*)&p5;
            pk1.z = *(uint32_t*)&p6; pk1.w = *(uint32_t*)&p7;
            *(uint4*)(dst + q * 16)     = pk0;
            *(uint4*)(dst + q * 16 + 8) = pk1;
        }
    }
}

// ===========================================================================
// Fused L1 SGEMM (K=13) + weight rounding (blockIdx.y >= 128). tw1 unpadded.
// ===========================================================================
#define RW_N0 131072
#define RW_N1 32768
#define RW_N2 (1024 * TOP_IN)
#define RW_N3 1048576
#define RW_N4 524288
#define RW_N5 131072
#define RW_TOTAL (RW_N0 + RW_N1 + RW_N2 + RW_N3 + RW_N4 + RW_N5)
#define RB_Y 128

__global__ __launch_bounds__(256, 2)
void l1_and_round(const float* __restrict__ A, const float* __restrict__ W,
                  const float* __restrict__ bias, __nv_bfloat16* __restrict__ C,
                  const float* __restrict__ bw2, const float* __restrict__ bw3,
                  const float* __restrict__ tw1, const float* __restrict__ tw2,
                  const float* __restrict__ tw3, const float* __restrict__ tw4,
                  __nv_bfloat16* __restrict__ d0, __nv_bfloat16* __restrict__ d1,
                  __nv_bfloat16* __restrict__ d2, __nv_bfloat16* __restrict__ d3,
                  __nv_bfloat16* __restrict__ d4, __nv_bfloat16* __restrict__ d5) {
    const int tid = threadIdx.x;

    if (blockIdx.y >= BATCH / 128) {
        const int nrb = 4 * RB_Y;
        const int rb = (blockIdx.y - BATCH / 128) * 4 + blockIdx.x;
        const int stride = nrb * 256;
        for (int i = rb * 256 + tid; i < RW_TOTAL; i += stride) {
            int j = i;
            if (j < RW_N0) { d0[j] = __float2bfloat16(bw2[j]); continue; }
            j -= RW_N0;
            if (j < RW_N1) { d1[j] = __float2bfloat16(bw3[j]); continue; }
            j -= RW_N1;
            if (j < RW_N2) { d2[j] = __float2bfloat16(tw1[j]); continue; }
            j -= RW_N2;
            if (j < RW_N3) { d3[j] = __float2bfloat16(tw2[j]); continue; }
            j -= RW_N3;
            if (j < RW_N4) { d4[j] = __float2bfloat16(tw3[j]); continue; }
            j -= RW_N4;
            d5[j] = __float2bfloat16(tw4[j]);
        }
        return;
    }

    const int N = 512, K = 13;
    __shared__ float As[8][132];
    __shared__ float Bs[8][132];
    const int bm = blockIdx.y * 128, bn = blockIdx.x * 128;
    const int tx = tid & 15, ty = tid >> 4;
    const int lk = tid & 7, lr = tid >> 3;

    float acc[8][8];
#pragma unroll
    for (int i = 0; i < 8; i++)
#pragma unroll
        for (int j = 0; j < 8; j++) acc[i][j] = 0.f;

    for (int k0 = 0; k0 < K; k0 += 8) {
        const int kk = k0 + lk;
        const bool kv = (kk < K);
#pragma unroll
        for (int p = 0; p < 4; p++) {
            const int row = lr + p * 32;
            As[lk][row] = kv ? A[(size_t)(bm + row) * K + kk] : 0.f;
            Bs[lk][row] = kv ? W[(size_t)(bn + row) * K + kk] : 0.f;
        }
        __syncthreads();
#pragma unroll
        for (int k = 0; k < 8; k++) {
            float4 a0 = *(const float4*)&As[k][ty * 4];
            float4 a1 = *(const float4*)&As[k][64 + ty * 4];
            float4 b0 = *(const float4*)&Bs[k][tx * 4];
            float4 b1 = *(const float4*)&Bs[k][64 + tx * 4];
            float a[8] = {a0.x, a0.y, a0.z, a0.w, a1.x, a1.y, a1.z, a1.w};
            float b[8] = {b0.x, b0.y, b0.z, b0.w, b1.x, b1.y, b1.z, b1.w};
#pragma unroll
            for (int i = 0; i < 8; i++)
#pragma unroll
                for (int j = 0; j < 8; j++)
                    acc[i][j] += a[i] * b[j];
        }
        __syncthreads();
    }
    const int rbase[2] = {bm + ty * 4, bm + 64 + ty * 4};
    const int cbase[2] = {bn + tx * 4, bn + 64 + tx * 4};
#pragma unroll
    for (int jh = 0; jh < 2; jh++) {
        const int col = cbase[jh];
        float4 bv = *(const float4*)&bias[col];
#pragma unroll
        for (int ih = 0; ih < 2; ih++) {
#pragma unroll
            for (int i = 0; i < 4; i++) {
                const int row = rbase[ih] + i;
                float4 v;
                v.x = acc[ih * 4 + i][jh * 4 + 0] + bv.x;
                v.y = acc[ih * 4 + i][jh * 4 + 1] + bv.y;
                v.z = acc[ih * 4 + i][jh * 4 + 2] + bv.z;
                v.w = acc[ih * 4 + i][jh * 4 + 3] + bv.w;
                v.x = v.x > 0.f ? v.x : 0.f;
                v.y = v.y > 0.f ? v.y : 0.f;
                v.z = v.z > 0.f ? v.z : 0.f;
                v.w = v.w > 0.f ? v.w : 0.f;
                __nv_bfloat162 p0 = __floats2bfloat162_rn(v.x, v.y);
                __nv_bfloat162 p1 = __floats2bfloat162_rn(v.z, v.w);
                uint2 pk; pk.x = *(uint32_t*)&p0; pk.y = *(uint32_t*)&p1;
                *(uint2*)&C[(size_t)row * N + col] = pk;
            }
        }
    }
}

// ===========================================================================
// interact5 (champion): warp-independent, register-batched gather.
// Output x is stride-480 (unpadded).
// ===========================================================================
#define IFE 136
#define INTERACT_SMEM (8 * 32 * IFE * 2)      // 69632

__global__ __launch_bounds__(256, 2)
void interact5(const __nv_bfloat16* __restrict__ bottom,
               const int* __restrict__ cat,
               const float* __restrict__ emb,
               __nv_bfloat16* __restrict__ x) {
    extern __shared__ __nv_bfloat16 ism[];
    const int warp = threadIdx.x >> 5, lane = threadIdx.x & 31;
    const int b = blockIdx.x * 8 + warp;
    __nv_bfloat16* fs = ism + (size_t)warp * 32 * IFE;

    int ci = 0;
    if (lane < NUM_CAT) ci = cat[(size_t)lane * BATCH + b];

    *(uint2*)(fs + lane * 4) = *(const uint2*)(bottom + (size_t)b * 128 + lane * 4);

    float4 v[13];
#pragma unroll
    for (int h = 0; h < 2; h++) {
#pragma unroll
        for (int r = 0; r < 13; r++) {
            const int tb = h * 13 + r;
            const int idx = __shfl_sync(0xffffffffu, ci, tb);
            v[r] = *(const float4*)(emb + ((size_t)tb * TABLE_SIZE + idx) * 128 + lane * 4);
        }
#pragma unroll
        for (int r = 0; r < 13; r++) {
            const int row = h * 13 + r + 1;
            __nv_bfloat162 p0 = __floats2bfloat162_rn(v[r].x, v[r].y);
            __nv_bfloat162 p1 = __floats2bfloat162_rn(v[r].z, v[r].w);
            uint2 pk; pk.x = *(uint32_t*)&p0; pk.y = *(uint32_t*)&p1;
            *(uint2*)(fs + (size_t)row * IFE + lane * 4) = pk;
        }
    }

    {
        uint2 z; z.x = 0u; z.y = 0u;
        for (int i = lane; i < 5 * IFE / 4; i += 32)
            *(uint2*)(fs + 27 * IFE + i * 4) = z;
    }
    __syncwarp();

    wmma::fragment<wmma::accumulator, 16, 16, 16, float> g00, g10, g11;
    wmma::fill_fragment(g00, 0.0f);
    wmma::fill_fragment(g10, 0.0f);
    wmma::fill_fragment(g11, 0.0f);
#pragma unroll
    for (int kk = 0; kk < 128; kk += 16) {
        wmma::fragment<wmma::matrix_a, 16, 16, 16, __nv_bfloat16, wmma::row_major> a0, a1;
        wmma::fragment<wmma::matrix_b, 16, 16, 16, __nv_bfloat16, wmma::col_major> b0, b1;
        wmma::load_matrix_sync(a0, fs + kk, IFE);
        wmma::load_matrix_sync(a1, fs + 16 * IFE + kk, IFE);
        wmma::load_matrix_sync(b0, fs + kk, IFE);
        wmma::load_matrix_sync(b1, fs + 16 * IFE + kk, IFE);
        wmma::mma_sync(g00, a0, b0, g00);
        wmma::mma_sync(g10, a1, b0, g10);
        wmma::mma_sync(g11, a1, b1, g11);
    }

    float* gs = (float*)fs;
    wmma::store_matrix_sync(gs, g00, 34, wmma::mem_row_major);
    wmma::store_matrix_sync(gs + 16 * 34, g10, 34, wmma::mem_row_major);
    wmma::store_matrix_sync(gs + 16 * 34 + 16, g11, 34, wmma::mem_row_major);
    __syncwarp();

    __nv_bfloat16* xb = x + (size_t)b * TOP_IN;
    *(uint2*)(xb + lane * 4) = *(const uint2*)(bottom + (size_t)b * 128 + lane * 4);
    if (lane == 0) xb[TOP_IN - 1] = __float2bfloat16(0.f);
    for (int p = lane; p < 351; p += 32) {
        int r = (int)((1.0f + sqrtf(8.0f * (float)p + 1.0f)) * 0.5f);
        if (r * (r - 1) / 2 > p) r--;
        if ((r + 1) * r / 2 <= p) r++;
        const int c = p - r * (r - 1) / 2;
        xb[128 + p] = __float2bfloat16(gs[r * 34 + c]);
    }
}

// ===========================================================================
// Final layer: sigmoid(dot(t4_bf16, w5) + b5). Warp per sample.
// ===========================================================================
__global__ __launch_bounds__(256)
void final_layer(const __nv_bfloat16* __restrict__ A,
                 const float* __restrict__ w5,
                 const float* __restrict__ b5, float* __restrict__ out) {
    const int gwarp = (blockIdx.x * blockDim.x + threadIdx.x) >> 5;
    const int lane = threadIdx.x & 31;
    if (gwarp >= BATCH) return;
    uint4 raw = *(const uint4*)(A + (size_t)gwarp * 256 + lane * 8);
    const float4* w4 = (const float4*)(w5 + lane * 8);
    float4 w0 = w4[0], w1 = w4[1];
    __nv_bfloat162 p0 = *(__nv_bfloat162*)&raw.x;
    __nv_bfloat162 p1 = *(__nv_bfloat162*)&raw.y;
    __nv_bfloat162 p2 = *(__nv_bfloat162*)&raw.z;
    __nv_bfloat162 p3 = *(__nv_bfloat162*)&raw.w;
    float s = __bfloat162float(p0.x) * w0.x + __bfloat162float(p0.y) * w0.y +
              __bfloat162float(p1.x) * w0.z + __bfloat162float(p1.y) * w0.w +
              __bfloat162float(p2.x) * w1.x + __bfloat162float(p2.y) * w1.y +
              __bfloat162float(p3.x) * w1.z + __bfloat162float(p3.y) * w1.w;
#pragma unroll
    for (int o = 16; o; o >>= 1) s += __shfl_xor_sync(0xffffffffu, s, o);
    if (lane == 0) out[gwarp] = 1.f / (1.f + expf(-(s + b5[0])));
}

// ===========================================================================
extern "C" void kernel_launch(void* const* d_in, const int* in_sizes, int n_in,
                              void* d_out, int out_size) {
    const float* num = (const float*)d_in[0];
    const int*   cat = (const int*)  d_in[1];
    const float* emb = (const float*)d_in[2];
    const float* bw1 = (const float*)d_in[3];
    const float* bb1 = (const float*)d_in[4];
    const float* bw2 = (const float*)d_in[5];
    const float* bb2 = (const float*)d_in[6];
    const float* bw3 = (const float*)d_in[7];
    const float* bb3 = (const float*)d_in[8];
    const float* tw1 = (const float*)d_in[9];
    const float* tb1 = (const float*)d_in[10];
    const float* tw2 = (const float*)d_in[11];
    const float* tb2 = (const float*)d_in[12];
    const float* tw3 = (const float*)d_in[13];
    const float* tb3 = (const float*)d_in[14];
    const float* tw4 = (const float*)d_in[15];
    const float* tb4 = (const float*)d_in[16];
    const float* tw5 = (const float*)d_in[17];
    const float* tb5 = (const float*)d_in[18];
    float* out = (float*)d_out;

    __nv_bfloat16 *h1, *h2, *bot, *x, *t1, *t2, *t3, *t4;
    __nv_bfloat16 *bw2r, *bw3r, *tw1r, *tw2r, *tw3r, *tw4r;
    cudaGetSymbolAddress((void**)&h1,  g_h1);
    cudaGetSymbolAddress((void**)&h2,  g_h2);
    cudaGetSymbolAddress((void**)&bot, g_bot);
    cudaGetSymbolAddress((void**)&x,   g_x);
    cudaGetSymbolAddress((void**)&t1,  g_t1);
    cudaGetSymbolAddress((void**)&t2,  g_t2);
    cudaGetSymbolAddress((void**)&t3,  g_t3);
    cudaGetSymbolAddress((void**)&t4,  g_t4);
    cudaGetSymbolAddress((void**)&bw2r, g_bw2r);
    cudaGetSymbolAddress((void**)&bw3r, g_bw3r);
    cudaGetSymbolAddress((void**)&tw1r, g_tw1r);
    cudaGetSymbolAddress((void**)&tw2r, g_tw2r);
    cudaGetSymbolAddress((void**)&tw3r, g_tw3r);
    cudaGetSymbolAddress((void**)&tw4r, g_tw4r);

    cudaFuncSetAttribute(bf16_gemm, cudaFuncAttributeMaxDynamicSharedMemorySize, GEMM_SMEM);
    cudaFuncSetAttribute(interact5, cudaFuncAttributeMaxDynamicSharedMemorySize, INTERACT_SMEM);

    const int MB = BATCH / 128;  // 128

    // launch 1: L1 SGEMM + weight rounding (fused)
    l1_and_round<<<dim3(4, MB + RB_Y), 256>>>(num, bw1, bb1, h1,
                                              bw2, bw3, tw1, tw2, tw3, tw4,
                                              bw2r, bw3r, tw1r, tw2r, tw3r, tw4r);

    // launches 2-3: bottom MLP
    bf16_gemm<<<dim3(2, MB), 128, GEMM_SMEM>>>(h1, bw2r, bb2, h2, 256, 512);
    bf16_gemm<<<dim3(1, MB), 128, GEMM_SMEM>>>(h2, bw3r, bb3, bot, 128, 256);

    // launch 4 (profiled): interaction
    interact5<<<BATCH / 8, 256, INTERACT_SMEM>>>(bot, cat, emb, x);

    // top MLP (T1 unpadded: K = 480, 480 % 32 == 0)
    bf16_gemm<<<dim3(8, MB), 128, GEMM_SMEM>>>(x,  tw1r, tb1, t1, 1024, TOP_IN);
    bf16_gemm<<<dim3(8, MB), 128, GEMM_SMEM>>>(t1, tw2r, tb2, t2, 1024, 1024);
    bf16_gemm<<<dim3(4, MB), 128, GEMM_SMEM>>>(t2, tw3r, tb3, t3, 512, 1024);
    bf16_gemm<<<dim3(2, MB), 128, GEMM_SMEM>>>(t3, tw4r, tb4, t4, 256, 512);

    // final dot + sigmoid
    final_layer<<<(BATCH * 32 + 255) / 256, 256>>>(t4, tw5, tb5, out);
}